// round 3
// baseline (speedup 1.0000x reference)
#include <cuda_runtime.h>
#include <cstdint>

// ---------------------------------------------------------------------------
// SchNet interaction block, fused fp32 implementation.
//   K1: v = x@lin1_w + lin1_b           (also zeroes g_agg)
//   K2: per-edge fused filter net + gather + modulate + scatter (red.v4.f32)
//   K3: out = x + (ssp(agg@lin2_w+b2))@lin3_w + b3
// edge_index is delivered as int32 by the harness (int64 inputs are downcast).
// ---------------------------------------------------------------------------

#define NW   16              // warps per block
#define TPB  (NW * 32)       // 512 threads
#define GRID 152             // 1 CTA per SM on GB300

#define N_NODES 100000
#define H 128

__device__ __align__(128) float g_v[N_NODES * H];
__device__ __align__(128) float g_agg[N_NODES * H];

__device__ __forceinline__ float sspf(float z) {
    // softplus(z) - ln2, numerically stable
    return fmaxf(z, 0.0f) + log1pf(expf(-fabsf(z))) - 0.69314718055994530942f;
}
__device__ __forceinline__ float4 ssp4(float4 a) {
    return make_float4(sspf(a.x), sspf(a.y), sspf(a.z), sspf(a.w));
}
__device__ __forceinline__ float4 f4zero() { return make_float4(0.f, 0.f, 0.f, 0.f); }

// ---------------------------------------------------------------------------
// K1: node projection  v[n] = x[n] @ lin1_w + lin1_b ; g_agg[n] = 0
// ---------------------------------------------------------------------------
__global__ void __launch_bounds__(TPB, 1)
k_vproj(const float* __restrict__ x, const float* __restrict__ w,
        const float* __restrict__ b, int N)
{
    extern __shared__ float sm[];
    float* sw = sm;                       // 128*128
    float* sb = sw + 128 * 128;           // 128
    float* sx = sb + 128;                 // NW*4*128

    for (int i = threadIdx.x; i < 128 * 128 / 4; i += TPB)
        ((float4*)sw)[i] = ((const float4*)w)[i];
    for (int i = threadIdx.x; i < 32; i += TPB)
        ((float4*)sb)[i] = ((const float4*)b)[i];
    __syncthreads();

    const int wid = threadIdx.x >> 5, l = threadIdx.x & 31;
    float* sxw = sx + wid * 4 * 128;
    const long stride = (long)gridDim.x * NW * 4;

    for (long base = (long)(blockIdx.x * NW + wid) * 4; base < N; base += stride) {
        for (int i = l; i < 128; i += 32) {
            int e = i >> 5, q = i & 31;
            long r = base + e;
            ((float4*)sxw)[e * 32 + q] =
                (r < N) ? ((const float4*)x)[r * 32 + q] : f4zero();
        }
        __syncwarp();

        float4 bb = ((float4*)sb)[l];
        float4 acc[4] = {bb, bb, bb, bb};
#pragma unroll 8
        for (int k = 0; k < 128; k++) {
            float4 wv = ((float4*)sw)[k * 32 + l];
            float e0 = sxw[k], e1 = sxw[128 + k], e2 = sxw[256 + k], e3 = sxw[384 + k];
            acc[0].x += e0 * wv.x; acc[0].y += e0 * wv.y; acc[0].z += e0 * wv.z; acc[0].w += e0 * wv.w;
            acc[1].x += e1 * wv.x; acc[1].y += e1 * wv.y; acc[1].z += e1 * wv.z; acc[1].w += e1 * wv.w;
            acc[2].x += e2 * wv.x; acc[2].y += e2 * wv.y; acc[2].z += e2 * wv.z; acc[2].w += e2 * wv.w;
            acc[3].x += e3 * wv.x; acc[3].y += e3 * wv.y; acc[3].z += e3 * wv.z; acc[3].w += e3 * wv.w;
        }
#pragma unroll
        for (int e = 0; e < 4; e++) {
            long r = base + e;
            if (r < N) {
                ((float4*)g_v)[r * 32 + l]   = acc[e];
                ((float4*)g_agg)[r * 32 + l] = f4zero();
            }
        }
        __syncwarp();
    }
}

// ---------------------------------------------------------------------------
// K2: fused edge pipeline.
//   h1 = ssp(ea @ cf1_w); h2 = ssp(h1 @ cf2_w + cf2_b)
//   msg = g_v[src] * h2 * ew ; red.add.v4 into g_agg[dst]
// edge_index as int32: src = ei[r], dst = ei[E + r].
// ---------------------------------------------------------------------------
__global__ void __launch_bounds__(TPB, 1)
k_edge(const float* __restrict__ ea, const float* __restrict__ ew,
       const float* __restrict__ cf1, const float* __restrict__ cf2,
       const float* __restrict__ cf2b, const int* __restrict__ ei,
       int E, int N)
{
    extern __shared__ float sm[];
    float* s1  = sm;                        // 64*128
    float* s2  = s1 + 64 * 128;             // 128*128
    float* sb  = s2 + 128 * 128;            // 128
    float* sea = sb + 128;                  // NW*4*64
    float* sh  = sea + NW * 4 * 64;         // NW*4*128

    for (int i = threadIdx.x; i < 64 * 128 / 4; i += TPB)
        ((float4*)s1)[i] = ((const float4*)cf1)[i];
    for (int i = threadIdx.x; i < 128 * 128 / 4; i += TPB)
        ((float4*)s2)[i] = ((const float4*)cf2)[i];
    for (int i = threadIdx.x; i < 32; i += TPB)
        ((float4*)sb)[i] = ((const float4*)cf2b)[i];
    __syncthreads();

    const int wid = threadIdx.x >> 5, l = threadIdx.x & 31;
    float* seaw = sea + wid * 256;   // 4 * 64
    float* shw  = sh  + wid * 512;   // 4 * 128
    const int* srcp = ei;
    const int* dstp = ei + E;
    const long stride = (long)gridDim.x * NW * 4;

    for (long base = (long)(blockIdx.x * NW + wid) * 4; base < E; base += stride) {
        for (int i = l; i < 64; i += 32) {
            int e = i >> 4, q = i & 15;
            long r = base + e;
            ((float4*)seaw)[e * 16 + q] =
                (r < E) ? ((const float4*)ea)[r * 16 + q] : f4zero();
        }
        __syncwarp();

        // stage 1: [4,64] @ [64,128]
        float4 a[4] = {f4zero(), f4zero(), f4zero(), f4zero()};
#pragma unroll 8
        for (int k = 0; k < 64; k++) {
            float4 wv = ((float4*)s1)[k * 32 + l];
            float e0 = seaw[k], e1 = seaw[64 + k], e2 = seaw[128 + k], e3 = seaw[192 + k];
            a[0].x += e0 * wv.x; a[0].y += e0 * wv.y; a[0].z += e0 * wv.z; a[0].w += e0 * wv.w;
            a[1].x += e1 * wv.x; a[1].y += e1 * wv.y; a[1].z += e1 * wv.z; a[1].w += e1 * wv.w;
            a[2].x += e2 * wv.x; a[2].y += e2 * wv.y; a[2].z += e2 * wv.z; a[2].w += e2 * wv.w;
            a[3].x += e3 * wv.x; a[3].y += e3 * wv.y; a[3].z += e3 * wv.z; a[3].w += e3 * wv.w;
        }
#pragma unroll
        for (int e = 0; e < 4; e++)
            ((float4*)shw)[e * 32 + l] = ssp4(a[e]);
        __syncwarp();

        // stage 2: [4,128] @ [128,128] + bias
        float4 c[4] = {f4zero(), f4zero(), f4zero(), f4zero()};
#pragma unroll 8
        for (int k = 0; k < 128; k++) {
            float4 wv = ((float4*)s2)[k * 32 + l];
            float e0 = shw[k], e1 = shw[128 + k], e2 = shw[256 + k], e3 = shw[384 + k];
            c[0].x += e0 * wv.x; c[0].y += e0 * wv.y; c[0].z += e0 * wv.z; c[0].w += e0 * wv.w;
            c[1].x += e1 * wv.x; c[1].y += e1 * wv.y; c[1].z += e1 * wv.z; c[1].w += e1 * wv.w;
            c[2].x += e2 * wv.x; c[2].y += e2 * wv.y; c[2].z += e2 * wv.z; c[2].w += e2 * wv.w;
            c[3].x += e3 * wv.x; c[3].y += e3 * wv.y; c[3].z += e3 * wv.z; c[3].w += e3 * wv.w;
        }
        float4 bb = ((float4*)sb)[l];

#pragma unroll
        for (int e = 0; e < 4; e++) {
            long r = base + e;
            if (r >= E) break;
            float4 h2 = ssp4(make_float4(c[e].x + bb.x, c[e].y + bb.y,
                                         c[e].z + bb.z, c[e].w + bb.w));
            int s = srcp[r];
            int d = dstp[r];
            // defensive: if dtype assumption is wrong this yields wrong numbers,
            // not a crash (diagnosable via rel_err instead of IMA)
            if ((unsigned)s >= (unsigned)N || (unsigned)d >= (unsigned)N) continue;
            float wg = ew[r];
            float4 vv = ((const float4*)g_v)[(long)s * 32 + l];
            float4 m = make_float4(vv.x * h2.x * wg, vv.y * h2.y * wg,
                                   vv.z * h2.z * wg, vv.w * h2.w * wg);
            float* p = &g_agg[(long)d * 128 + l * 4];
            asm volatile("red.global.add.v4.f32 [%0], {%1, %2, %3, %4};"
                         :: "l"(p), "f"(m.x), "f"(m.y), "f"(m.z), "f"(m.w)
                         : "memory");
        }
        __syncwarp();
    }
}

// ---------------------------------------------------------------------------
// K3: out = x + ssp(agg @ lin2_w + b2) @ lin3_w + b3
// ---------------------------------------------------------------------------
__global__ void __launch_bounds__(TPB, 1)
k_post(const float* __restrict__ x,
       const float* __restrict__ w2, const float* __restrict__ b2,
       const float* __restrict__ w3, const float* __restrict__ b3,
       float* __restrict__ out, int N)
{
    extern __shared__ float sm[];
    float* sw2 = sm;                       // 128*128
    float* sw3 = sw2 + 128 * 128;          // 128*128
    float* sb2 = sw3 + 128 * 128;          // 128
    float* sb3 = sb2 + 128;                // 128
    float* st  = sb3 + 128;                // NW*4*128

    for (int i = threadIdx.x; i < 128 * 128 / 4; i += TPB) {
        ((float4*)sw2)[i] = ((const float4*)w2)[i];
        ((float4*)sw3)[i] = ((const float4*)w3)[i];
    }
    for (int i = threadIdx.x; i < 32; i += TPB) {
        ((float4*)sb2)[i] = ((const float4*)b2)[i];
        ((float4*)sb3)[i] = ((const float4*)b3)[i];
    }
    __syncthreads();

    const int wid = threadIdx.x >> 5, l = threadIdx.x & 31;
    float* stw = st + wid * 512;
    const long stride = (long)gridDim.x * NW * 4;

    for (long base = (long)(blockIdx.x * NW + wid) * 4; base < N; base += stride) {
        for (int i = l; i < 128; i += 32) {
            int e = i >> 5, q = i & 31;
            long r = base + e;
            ((float4*)stw)[e * 32 + q] =
                (r < N) ? ((const float4*)g_agg)[r * 32 + q] : f4zero();
        }
        __syncwarp();

        float4 bb2 = ((float4*)sb2)[l];
        float4 a[4] = {bb2, bb2, bb2, bb2};
#pragma unroll 8
        for (int k = 0; k < 128; k++) {
            float4 wv = ((float4*)sw2)[k * 32 + l];
            float e0 = stw[k], e1 = stw[128 + k], e2 = stw[256 + k], e3 = stw[384 + k];
            a[0].x += e0 * wv.x; a[0].y += e0 * wv.y; a[0].z += e0 * wv.z; a[0].w += e0 * wv.w;
            a[1].x += e1 * wv.x; a[1].y += e1 * wv.y; a[1].z += e1 * wv.z; a[1].w += e1 * wv.w;
            a[2].x += e2 * wv.x; a[2].y += e2 * wv.y; a[2].z += e2 * wv.z; a[2].w += e2 * wv.w;
            a[3].x += e3 * wv.x; a[3].y += e3 * wv.y; a[3].z += e3 * wv.z; a[3].w += e3 * wv.w;
        }
        __syncwarp();
#pragma unroll
        for (int e = 0; e < 4; e++)
            ((float4*)stw)[e * 32 + l] = ssp4(a[e]);
        __syncwarp();

        float4 bb3 = ((float4*)sb3)[l];
        float4 c[4] = {bb3, bb3, bb3, bb3};
#pragma unroll 8
        for (int k = 0; k < 128; k++) {
            float4 wv = ((float4*)sw3)[k * 32 + l];
            float e0 = stw[k], e1 = stw[128 + k], e2 = stw[256 + k], e3 = stw[384 + k];
            c[0].x += e0 * wv.x; c[0].y += e0 * wv.y; c[0].z += e0 * wv.z; c[0].w += e0 * wv.w;
            c[1].x += e1 * wv.x; c[1].y += e1 * wv.y; c[1].z += e1 * wv.z; c[1].w += e1 * wv.w;
            c[2].x += e2 * wv.x; c[2].y += e2 * wv.y; c[2].z += e2 * wv.z; c[2].w += e2 * wv.w;
            c[3].x += e3 * wv.x; c[3].y += e3 * wv.y; c[3].z += e3 * wv.z; c[3].w += e3 * wv.w;
        }
#pragma unroll
        for (int e = 0; e < 4; e++) {
            long r = base + e;
            if (r < N) {
                float4 xv = ((const float4*)x)[r * 32 + l];
                ((float4*)out)[r * 32 + l] =
                    make_float4(xv.x + c[e].x, xv.y + c[e].y,
                                xv.z + c[e].z, xv.w + c[e].w);
            }
        }
        __syncwarp();
    }
}

// ---------------------------------------------------------------------------

static const int SMEM1 = (128 * 128 + 128 + NW * 4 * 128) * 4;
static const int SMEM2 = (64 * 128 + 128 * 128 + 128 + NW * 4 * 64 + NW * 4 * 128) * 4;
static const int SMEM3 = (2 * 128 * 128 + 256 + NW * 4 * 128) * 4;

extern "C" void kernel_launch(void* const* d_in, const int* in_sizes, int n_in,
                              void* d_out, int out_size)
{
    const float* x    = (const float*)d_in[0];
    const float* ea   = (const float*)d_in[1];
    const float* ew   = (const float*)d_in[2];
    const float* l1w  = (const float*)d_in[3];
    const float* l1b  = (const float*)d_in[4];
    const float* cf1  = (const float*)d_in[5];
    const float* cf2  = (const float*)d_in[6];
    const float* cf2b = (const float*)d_in[7];
    const float* l2w  = (const float*)d_in[8];
    const float* l2b  = (const float*)d_in[9];
    const float* l3w  = (const float*)d_in[10];
    const float* l3b  = (const float*)d_in[11];
    const int*   ei   = (const int*)d_in[12];   // int64 downcast to int32 by harness

    int N = in_sizes[0] / 128;
    int E = in_sizes[1] / 64;

    cudaFuncSetAttribute(k_vproj, cudaFuncAttributeMaxDynamicSharedMemorySize, SMEM1);
    cudaFuncSetAttribute(k_edge,  cudaFuncAttributeMaxDynamicSharedMemorySize, SMEM2);
    cudaFuncSetAttribute(k_post,  cudaFuncAttributeMaxDynamicSharedMemorySize, SMEM3);

    k_vproj<<<GRID, TPB, SMEM1>>>(x, l1w, l1b, N);
    k_edge <<<GRID, TPB, SMEM2>>>(ea, ew, cf1, cf2, cf2b, ei, E, N);
    k_post <<<GRID, TPB, SMEM3>>>(x, l2w, l2b, l3w, l3b, (float*)d_out, N);
}

// round 7
// speedup vs baseline: 1.4504x; 1.4504x over previous
#include <cuda_runtime.h>
#include <cstdint>

// ---------------------------------------------------------------------------
// SchNet interaction block.
//   K1: v = x@lin1_w + lin1_b ; zero g_agg            (fp32 FFMA)
//   K2: edge filter net via mma.sync m16n8k8 tf32 + gather/modulate/scatter
//   K3: out = x + ssp(agg@lin2_w+b2)@lin3_w + b3      (fp32 FFMA)
// Base-target sm_103: NO tcgen05 (ptxas rejects); mma.sync is arch-neutral.
// edge_index delivered as int32 (verified R3).
// ---------------------------------------------------------------------------

#define NW   16
#define TPB  (NW * 32)
#define GRID 152

#define N_NODES 100000
#define H 128

__device__ __align__(128) float g_v[N_NODES * H];
__device__ __align__(128) float g_agg[N_NODES * H];

#define LN2F 0.69314718055994530942f
#define L2EF 1.44269504088896340736f

__device__ __forceinline__ float ex2f(float x) {
    float r; asm("ex2.approx.f32 %0, %1;" : "=f"(r) : "f"(x)); return r;
}
__device__ __forceinline__ float lg2f(float x) {
    float r; asm("lg2.approx.f32 %0, %1;" : "=f"(r) : "f"(x)); return r;
}
__device__ __forceinline__ float sspf(float z) {
    // softplus(z) - ln2 = max(z,0) + ln(1+e^{-|z|}) - ln2, via MUFU EX2/LG2
    float t = ex2f(-fabsf(z) * L2EF);
    float u = lg2f(1.0f + t);
    return fmaxf(z, 0.0f) + fmaf(u, LN2F, -LN2F);
}
__device__ __forceinline__ float4 ssp4(float4 a) {
    return make_float4(sspf(a.x), sspf(a.y), sspf(a.z), sspf(a.w));
}
__device__ __forceinline__ float4 f4zero() { return make_float4(0.f, 0.f, 0.f, 0.f); }

__device__ __forceinline__ uint32_t cvt_tf32(float x) {
    uint32_t r; asm("cvt.rna.tf32.f32 %0, %1;" : "=r"(r) : "f"(x)); return r;
}
__device__ __forceinline__ void mma_tf32(float c[4], const uint32_t a[4],
                                         uint32_t b0, uint32_t b1) {
    asm volatile("mma.sync.aligned.m16n8k8.row.col.f32.tf32.tf32.f32 "
                 "{%0,%1,%2,%3}, {%4,%5,%6,%7}, {%8,%9}, {%0,%1,%2,%3};"
                 : "+f"(c[0]), "+f"(c[1]), "+f"(c[2]), "+f"(c[3])
                 : "r"(a[0]), "r"(a[1]), "r"(a[2]), "r"(a[3]), "r"(b0), "r"(b1));
}
__device__ __forceinline__ float quad_pick(float v0, float v1, int src, int odd) {
    float s0 = __shfl_sync(0xffffffffu, v0, src);
    float s1 = __shfl_sync(0xffffffffu, v1, src);
    return odd ? s1 : s0;
}
__device__ __forceinline__ void red2(float* p, float m0, float m1) {
    asm volatile("red.global.add.v2.f32 [%0], {%1, %2};"
                 :: "l"(p), "f"(m0), "f"(m1) : "memory");
}

// ---------------------------------------------------------------------------
// K1: node projection (R3-passing version, unchanged)
// ---------------------------------------------------------------------------
__global__ void __launch_bounds__(TPB, 1)
k_vproj(const float* __restrict__ x, const float* __restrict__ w,
        const float* __restrict__ b, int N)
{
    extern __shared__ float sm[];
    float* sw = sm;
    float* sb = sw + 128 * 128;
    float* sx = sb + 128;

    for (int i = threadIdx.x; i < 128 * 128 / 4; i += TPB)
        ((float4*)sw)[i] = ((const float4*)w)[i];
    for (int i = threadIdx.x; i < 32; i += TPB)
        ((float4*)sb)[i] = ((const float4*)b)[i];
    __syncthreads();

    const int wid = threadIdx.x >> 5, l = threadIdx.x & 31;
    float* sxw = sx + wid * 4 * 128;
    const long stride = (long)gridDim.x * NW * 4;

    for (long base = (long)(blockIdx.x * NW + wid) * 4; base < N; base += stride) {
        for (int i = l; i < 128; i += 32) {
            int e = i >> 5, q = i & 31;
            long r = base + e;
            ((float4*)sxw)[e * 32 + q] = (r < N) ? ((const float4*)x)[r * 32 + q] : f4zero();
        }
        __syncwarp();

        float4 bb = ((float4*)sb)[l];
        float4 acc[4] = {bb, bb, bb, bb};
#pragma unroll 8
        for (int k = 0; k < 128; k++) {
            float4 wv = ((float4*)sw)[k * 32 + l];
            float e0 = sxw[k], e1 = sxw[128 + k], e2 = sxw[256 + k], e3 = sxw[384 + k];
            acc[0].x += e0 * wv.x; acc[0].y += e0 * wv.y; acc[0].z += e0 * wv.z; acc[0].w += e0 * wv.w;
            acc[1].x += e1 * wv.x; acc[1].y += e1 * wv.y; acc[1].z += e1 * wv.z; acc[1].w += e1 * wv.w;
            acc[2].x += e2 * wv.x; acc[2].y += e2 * wv.y; acc[2].z += e2 * wv.z; acc[2].w += e2 * wv.w;
            acc[3].x += e3 * wv.x; acc[3].y += e3 * wv.y; acc[3].z += e3 * wv.z; acc[3].w += e3 * wv.w;
        }
#pragma unroll
        for (int e = 0; e < 4; e++) {
            long r = base + e;
            if (r < N) {
                ((float4*)g_v)[r * 32 + l]   = acc[e];
                ((float4*)g_agg)[r * 32 + l] = f4zero();
            }
        }
        __syncwarp();
    }
}

// ---------------------------------------------------------------------------
// K2: mma.sync tf32 edge kernel. 256 thr = 8 warps, each warp owns 32-edge
// tiles end-to-end (no cross-warp sync after weight staging).
//
// SMEM (u32 units):
//   sW1p  [ 8*16*64 ]  cf1 as tf32, pair-permuted blocks (kt,nt): 8x8 block
//                      stored [q][n8][half] so a B-frag is one lds.64
//   sW2p  [16*16*64 ]  cf2 likewise
//   sbias [128]        cf2_b (float)
// ---------------------------------------------------------------------------
#define W1U   (8 * 16 * 64)
#define W2U   (16 * 16 * 64)
#define OFFB  (W1U + W2U)
#define SMEM_E ((OFFB + 128) * 4)

__global__ void __launch_bounds__(256, 1)
k_edge_mma(const float* __restrict__ ea, const float* __restrict__ ew,
           const float* __restrict__ cf1, const float* __restrict__ cf2,
           const float* __restrict__ cf2b, const int* __restrict__ ei,
           int E, int N, int ntiles)
{
    extern __shared__ uint32_t smE[];
    uint32_t* sW1 = smE;
    uint32_t* sW2 = smE + W1U;
    float*    sbias = (float*)(smE + OFFB);

    const int tid = threadIdx.x;

    // ---- stage weights (tf32-converted, pair-permuted) ----
    for (int f = tid; f < W1U; f += 256) {
        int block = f >> 6, inner = f & 63;
        int kt = block >> 4, nt = block & 15;
        int qq = inner >> 4, rem = inner & 15, n8 = rem >> 1, half = rem & 1;
        int k = kt * 8 + qq + half * 4, n = nt * 8 + n8;
        sW1[f] = cvt_tf32(cf1[k * 128 + n]);
    }
    for (int f = tid; f < W2U; f += 256) {
        int block = f >> 6, inner = f & 63;
        int kt = block >> 4, nt = block & 15;
        int qq = inner >> 4, rem = inner & 15, n8 = rem >> 1, half = rem & 1;
        int k = kt * 8 + qq + half * 4, n = nt * 8 + n8;
        sW2[f] = cvt_tf32(cf2[k * 128 + n]);
    }
    if (tid < 128) sbias[tid] = cf2b[tid];
    __syncthreads();

    const int wid = tid >> 5;
    const int lane = tid & 31;
    const int rg = lane >> 2;          // row group 0..7
    const int q = lane & 3;            // quad position
    const int odd = q & 1;
    const int srcA = (lane & ~3) | (q >> 1);
    const int srcB = srcA + 2;
    const int boff = q * 16 + rg * 2;  // B-frag lds.64 offset within 64-u32 block

    const long wstride = (long)gridDim.x * 8;

    for (long tile = (long)blockIdx.x * 8 + wid; tile < ntiles; tile += wstride) {
        const long tb = tile * 32;

        // ================= stage 1: C1 = EA @ W1 =================
        float c1[2][16][4];
#pragma unroll
        for (int mt = 0; mt < 2; mt++)
#pragma unroll
            for (int nt = 0; nt < 16; nt++)
#pragma unroll
                for (int i = 0; i < 4; i++) c1[mt][nt][i] = 0.f;

#pragma unroll
        for (int kt = 0; kt < 8; kt++) {
            uint32_t a[2][4];
#pragma unroll
            for (int mt = 0; mt < 2; mt++) {
                long r0 = tb + mt * 16 + rg;
                long r1 = r0 + 8;
                bool v0 = r0 < E, v1 = r1 < E;
                const float* p0 = ea + r0 * 64 + kt * 8 + q;
                const float* p1 = ea + r1 * 64 + kt * 8 + q;
                a[mt][0] = cvt_tf32(v0 ? __ldg(p0)     : 0.f);
                a[mt][1] = cvt_tf32(v1 ? __ldg(p1)     : 0.f);
                a[mt][2] = cvt_tf32(v0 ? __ldg(p0 + 4) : 0.f);
                a[mt][3] = cvt_tf32(v1 ? __ldg(p1 + 4) : 0.f);
            }
#pragma unroll
            for (int nt = 0; nt < 16; nt++) {
                uint2 bb = *(const uint2*)(sW1 + (kt * 16 + nt) * 64 + boff);
                mma_tf32(c1[0][nt], a[0], bb.x, bb.y);
                mma_tf32(c1[1][nt], a[1], bb.x, bb.y);
            }
        }

        // h1 = ssp(C1), converted to tf32 bits in-place (shuffled as floats)
#pragma unroll
        for (int mt = 0; mt < 2; mt++)
#pragma unroll
            for (int nt = 0; nt < 16; nt++)
#pragma unroll
                for (int i = 0; i < 4; i++)
                    c1[mt][nt][i] = __uint_as_float(cvt_tf32(sspf(c1[mt][nt][i])));

        // ================= stage 2: C2 = h1 @ W2 (n-halves) ================
#pragma unroll
        for (int nh = 0; nh < 2; nh++) {
            float c2[2][8][4];
#pragma unroll
            for (int mt = 0; mt < 2; mt++)
#pragma unroll
                for (int nt = 0; nt < 8; nt++)
#pragma unroll
                    for (int i = 0; i < 4; i++) c2[mt][nt][i] = 0.f;

#pragma unroll
            for (int kt = 0; kt < 16; kt++) {
                uint32_t a[2][4];
#pragma unroll
                for (int mt = 0; mt < 2; mt++) {
                    // C(m16n8) frag -> A(m16k8) frag: quad permutation
                    a[mt][0] = __float_as_uint(quad_pick(c1[mt][kt][0], c1[mt][kt][1], srcA, odd));
                    a[mt][1] = __float_as_uint(quad_pick(c1[mt][kt][2], c1[mt][kt][3], srcA, odd));
                    a[mt][2] = __float_as_uint(quad_pick(c1[mt][kt][0], c1[mt][kt][1], srcB, odd));
                    a[mt][3] = __float_as_uint(quad_pick(c1[mt][kt][2], c1[mt][kt][3], srcB, odd));
                }
#pragma unroll
                for (int nt = 0; nt < 8; nt++) {
                    uint2 bb = *(const uint2*)(sW2 + (kt * 16 + nh * 8 + nt) * 64 + boff);
                    mma_tf32(c2[0][nt], a[0], bb.x, bb.y);
                    mma_tf32(c2[1][nt], a[1], bb.x, bb.y);
                }
            }

            // ---- epilogue: h2 = ssp(C2+bias); msg = v[src]*h2*ew -> red ----
#pragma unroll
            for (int mt = 0; mt < 2; mt++) {
                long e0 = tb + mt * 16 + rg;
                long e1 = e0 + 8;
                bool v0 = e0 < E, v1 = e1 < E;
                int s0 = 0, d0 = 0, s1 = 0, d1 = 0;
                float w0 = 0.f, w1 = 0.f;
                if (v0) {
                    s0 = ei[e0]; d0 = ei[E + e0]; w0 = ew[e0];
                    if ((unsigned)s0 >= (unsigned)N || (unsigned)d0 >= (unsigned)N) v0 = false;
                }
                if (v1) {
                    s1 = ei[e1]; d1 = ei[E + e1]; w1 = ew[e1];
                    if ((unsigned)s1 >= (unsigned)N || (unsigned)d1 >= (unsigned)N) v1 = false;
                }
#pragma unroll
                for (int nt = 0; nt < 8; nt++) {
                    int cn = nh * 64 + nt * 8 + 2 * q;
                    float bf0 = sbias[cn], bf1 = sbias[cn + 1];
                    if (v0) {
                        float h0 = sspf(c2[mt][nt][0] + bf0);
                        float h1 = sspf(c2[mt][nt][1] + bf1);
                        float2 vv = *(const float2*)&g_v[(long)s0 * 128 + cn];
                        red2(&g_agg[(long)d0 * 128 + cn], vv.x * h0 * w0, vv.y * h1 * w0);
                    }
                    if (v1) {
                        float h0 = sspf(c2[mt][nt][2] + bf0);
                        float h1 = sspf(c2[mt][nt][3] + bf1);
                        float2 vv = *(const float2*)&g_v[(long)s1 * 128 + cn];
                        red2(&g_agg[(long)d1 * 128 + cn], vv.x * h0 * w1, vv.y * h1 * w1);
                    }
                }
            }
        }
    }
}

// ---------------------------------------------------------------------------
// K3: post MLP + residual (R3-passing version, unchanged)
// ---------------------------------------------------------------------------
__global__ void __launch_bounds__(TPB, 1)
k_post(const float* __restrict__ x,
       const float* __restrict__ w2, const float* __restrict__ b2,
       const float* __restrict__ w3, const float* __restrict__ b3,
       float* __restrict__ out, int N)
{
    extern __shared__ float sm[];
    float* sw2 = sm;
    float* sw3 = sw2 + 128 * 128;
    float* sb2 = sw3 + 128 * 128;
    float* sb3 = sb2 + 128;
    float* st  = sb3 + 128;

    for (int i = threadIdx.x; i < 128 * 128 / 4; i += TPB) {
        ((float4*)sw2)[i] = ((const float4*)w2)[i];
        ((float4*)sw3)[i] = ((const float4*)w3)[i];
    }
    for (int i = threadIdx.x; i < 32; i += TPB) {
        ((float4*)sb2)[i] = ((const float4*)b2)[i];
        ((float4*)sb3)[i] = ((const float4*)b3)[i];
    }
    __syncthreads();

    const int wid = threadIdx.x >> 5, l = threadIdx.x & 31;
    float* stw = st + wid * 512;
    const long stride = (long)gridDim.x * NW * 4;

    for (long base = (long)(blockIdx.x * NW + wid) * 4; base < N; base += stride) {
        for (int i = l; i < 128; i += 32) {
            int e = i >> 5, qq = i & 31;
            long r = base + e;
            ((float4*)stw)[e * 32 + qq] = (r < N) ? ((const float4*)g_agg)[r * 32 + qq] : f4zero();
        }
        __syncwarp();

        float4 bb2 = ((float4*)sb2)[l];
        float4 a[4] = {bb2, bb2, bb2, bb2};
#pragma unroll 8
        for (int k = 0; k < 128; k++) {
            float4 wv = ((float4*)sw2)[k * 32 + l];
            float e0 = stw[k], e1 = stw[128 + k], e2 = stw[256 + k], e3 = stw[384 + k];
            a[0].x += e0 * wv.x; a[0].y += e0 * wv.y; a[0].z += e0 * wv.z; a[0].w += e0 * wv.w;
            a[1].x += e1 * wv.x; a[1].y += e1 * wv.y; a[1].z += e1 * wv.z; a[1].w += e1 * wv.w;
            a[2].x += e2 * wv.x; a[2].y += e2 * wv.y; a[2].z += e2 * wv.z; a[2].w += e2 * wv.w;
            a[3].x += e3 * wv.x; a[3].y += e3 * wv.y; a[3].z += e3 * wv.z; a[3].w += e3 * wv.w;
        }
        __syncwarp();
#pragma unroll
        for (int e = 0; e < 4; e++)
            ((float4*)stw)[e * 32 + l] = ssp4(a[e]);
        __syncwarp();

        float4 bb3 = ((float4*)sb3)[l];
        float4 c[4] = {bb3, bb3, bb3, bb3};
#pragma unroll 8
        for (int k = 0; k < 128; k++) {
            float4 wv = ((float4*)sw3)[k * 32 + l];
            float e0 = stw[k], e1 = stw[128 + k], e2 = stw[256 + k], e3 = stw[384 + k];
            c[0].x += e0 * wv.x; c[0].y += e0 * wv.y; c[0].z += e0 * wv.z; c[0].w += e0 * wv.w;
            c[1].x += e1 * wv.x; c[1].y += e1 * wv.y; c[1].z += e1 * wv.z; c[1].w += e1 * wv.w;
            c[2].x += e2 * wv.x; c[2].y += e2 * wv.y; c[2].z += e2 * wv.z; c[2].w += e2 * wv.w;
            c[3].x += e3 * wv.x; c[3].y += e3 * wv.y; c[3].z += e3 * wv.z; c[3].w += e3 * wv.w;
        }
#pragma unroll
        for (int e = 0; e < 4; e++) {
            long r = base + e;
            if (r < N) {
                float4 xv = ((const float4*)x)[r * 32 + l];
                ((float4*)out)[r * 32 + l] =
                    make_float4(xv.x + c[e].x, xv.y + c[e].y, xv.z + c[e].z, xv.w + c[e].w);
            }
        }
        __syncwarp();
    }
}

// ---------------------------------------------------------------------------

static const int SMEM1 = (128 * 128 + 128 + NW * 4 * 128) * 4;
static const int SMEM3 = (2 * 128 * 128 + 256 + NW * 4 * 128) * 4;

extern "C" void kernel_launch(void* const* d_in, const int* in_sizes, int n_in,
                              void* d_out, int out_size)
{
    const float* x    = (const float*)d_in[0];
    const float* ea   = (const float*)d_in[1];
    const float* ew   = (const float*)d_in[2];
    const float* l1w  = (const float*)d_in[3];
    const float* l1b  = (const float*)d_in[4];
    const float* cf1  = (const float*)d_in[5];
    const float* cf2  = (const float*)d_in[6];
    const float* cf2b = (const float*)d_in[7];
    const float* l2w  = (const float*)d_in[8];
    const float* l2b  = (const float*)d_in[9];
    const float* l3w  = (const float*)d_in[10];
    const float* l3b  = (const float*)d_in[11];
    const int*   ei   = (const int*)d_in[12];

    int N = in_sizes[0] / 128;
    int E = in_sizes[1] / 64;
    int ntiles = (E + 31) / 32;

    cudaFuncSetAttribute(k_vproj,    cudaFuncAttributeMaxDynamicSharedMemorySize, SMEM1);
    cudaFuncSetAttribute(k_edge_mma, cudaFuncAttributeMaxDynamicSharedMemorySize, SMEM_E);
    cudaFuncSetAttribute(k_post,     cudaFuncAttributeMaxDynamicSharedMemorySize, SMEM3);

    k_vproj   <<<GRID, TPB, SMEM1>>>(x, l1w, l1b, N);
    k_edge_mma<<<148, 256, SMEM_E>>>(ea, ew, cf1, cf2, cf2b, ei, E, N, ntiles);
    k_post    <<<GRID, TPB, SMEM3>>>(x, l2w, l2b, l3w, l3b, (float*)d_out, N);
}

// round 10
// speedup vs baseline: 1.6171x; 1.1149x over previous
#include <cuda_runtime.h>
#include <cstdint>

// ---------------------------------------------------------------------------
// SchNet interaction block.
//   K0: pre-permute cf1/cf2 into tf32 global scratch (b-frag friendly)
//   K1: v = x@lin1_w + lin1_b ; zero g_agg            (fp32 FFMA)
//   K2: edge filter net via mma.sync m16n8k8 tf32 + gather/modulate/scatter
//       weights from L1-resident global, 16-edge warp tiles, 2 CTA/SM
//   K3: out = x + ssp(agg@lin2_w+b2)@lin3_w + b3      (fp32 FFMA)
// Base-target sm_103: mma.sync only (no tcgen05). edge_index = int32.
// (Identical to R8 submission — R9 failed on infra, never ran.)
// ---------------------------------------------------------------------------

#define NW   16
#define TPB  (NW * 32)
#define GRID 152

#define N_NODES 100000
#define H 128

#define W1U   (8 * 16 * 64)     // 8192 u32
#define W2U   (16 * 16 * 64)    // 16384 u32

__device__ __align__(128) float g_v[N_NODES * H];
__device__ __align__(128) float g_agg[N_NODES * H];
__device__ __align__(128) uint32_t g_w1p[W1U];
__device__ __align__(128) uint32_t g_w2p[W2U];

#define LN2F 0.69314718055994530942f
#define L2EF 1.44269504088896340736f

__device__ __forceinline__ float ex2f(float x) {
    float r; asm("ex2.approx.f32 %0, %1;" : "=f"(r) : "f"(x)); return r;
}
__device__ __forceinline__ float lg2f(float x) {
    float r; asm("lg2.approx.f32 %0, %1;" : "=f"(r) : "f"(x)); return r;
}
__device__ __forceinline__ float sspf(float z) {
    float t = ex2f(-fabsf(z) * L2EF);
    float u = lg2f(1.0f + t);
    return fmaxf(z, 0.0f) + fmaf(u, LN2F, -LN2F);
}
__device__ __forceinline__ float4 ssp4(float4 a) {
    return make_float4(sspf(a.x), sspf(a.y), sspf(a.z), sspf(a.w));
}
__device__ __forceinline__ float4 f4zero() { return make_float4(0.f, 0.f, 0.f, 0.f); }

__device__ __forceinline__ uint32_t cvt_tf32(float x) {
    uint32_t r; asm("cvt.rna.tf32.f32 %0, %1;" : "=r"(r) : "f"(x)); return r;
}
__device__ __forceinline__ void mma_tf32(float c[4], const uint32_t a[4],
                                         uint32_t b0, uint32_t b1) {
    asm volatile("mma.sync.aligned.m16n8k8.row.col.f32.tf32.tf32.f32 "
                 "{%0,%1,%2,%3}, {%4,%5,%6,%7}, {%8,%9}, {%0,%1,%2,%3};"
                 : "+f"(c[0]), "+f"(c[1]), "+f"(c[2]), "+f"(c[3])
                 : "r"(a[0]), "r"(a[1]), "r"(a[2]), "r"(a[3]), "r"(b0), "r"(b1));
}
__device__ __forceinline__ float quad_pick(float v0, float v1, int src, int odd) {
    float s0 = __shfl_sync(0xffffffffu, v0, src);
    float s1 = __shfl_sync(0xffffffffu, v1, src);
    return odd ? s1 : s0;
}
__device__ __forceinline__ void red2(float* p, float m0, float m1) {
    asm volatile("red.global.add.v2.f32 [%0], {%1, %2};"
                 :: "l"(p), "f"(m0), "f"(m1) : "memory");
}

// ---------------------------------------------------------------------------
// K0: weight prep -> tf32, pair-permuted blocks so a b-frag is one ldg.64
// ---------------------------------------------------------------------------
__global__ void k_wprep(const float* __restrict__ cf1, const float* __restrict__ cf2)
{
    int stride = blockDim.x * gridDim.x;
    for (int f = blockIdx.x * blockDim.x + threadIdx.x; f < W1U; f += stride) {
        int block = f >> 6, inner = f & 63;
        int kt = block >> 4, nt = block & 15;
        int qq = inner >> 4, rem = inner & 15, n8 = rem >> 1, half = rem & 1;
        int k = kt * 8 + qq + half * 4, n = nt * 8 + n8;
        g_w1p[f] = cvt_tf32(cf1[k * 128 + n]);
    }
    for (int f = blockIdx.x * blockDim.x + threadIdx.x; f < W2U; f += stride) {
        int block = f >> 6, inner = f & 63;
        int kt = block >> 4, nt = block & 15;
        int qq = inner >> 4, rem = inner & 15, n8 = rem >> 1, half = rem & 1;
        int k = kt * 8 + qq + half * 4, n = nt * 8 + n8;
        g_w2p[f] = cvt_tf32(cf2[k * 128 + n]);
    }
}

// ---------------------------------------------------------------------------
// K1: node projection (R3-passing version, unchanged)
// ---------------------------------------------------------------------------
__global__ void __launch_bounds__(TPB, 1)
k_vproj(const float* __restrict__ x, const float* __restrict__ w,
        const float* __restrict__ b, int N)
{
    extern __shared__ float sm[];
    float* sw = sm;
    float* sb = sw + 128 * 128;
    float* sx = sb + 128;

    for (int i = threadIdx.x; i < 128 * 128 / 4; i += TPB)
        ((float4*)sw)[i] = ((const float4*)w)[i];
    for (int i = threadIdx.x; i < 32; i += TPB)
        ((float4*)sb)[i] = ((const float4*)b)[i];
    __syncthreads();

    const int wid = threadIdx.x >> 5, l = threadIdx.x & 31;
    float* sxw = sx + wid * 4 * 128;
    const long stride = (long)gridDim.x * NW * 4;

    for (long base = (long)(blockIdx.x * NW + wid) * 4; base < N; base += stride) {
        for (int i = l; i < 128; i += 32) {
            int e = i >> 5, q = i & 31;
            long r = base + e;
            ((float4*)sxw)[e * 32 + q] = (r < N) ? ((const float4*)x)[r * 32 + q] : f4zero();
        }
        __syncwarp();

        float4 bb = ((float4*)sb)[l];
        float4 acc[4] = {bb, bb, bb, bb};
#pragma unroll 8
        for (int k = 0; k < 128; k++) {
            float4 wv = ((float4*)sw)[k * 32 + l];
            float e0 = sxw[k], e1 = sxw[128 + k], e2 = sxw[256 + k], e3 = sxw[384 + k];
            acc[0].x += e0 * wv.x; acc[0].y += e0 * wv.y; acc[0].z += e0 * wv.z; acc[0].w += e0 * wv.w;
            acc[1].x += e1 * wv.x; acc[1].y += e1 * wv.y; acc[1].z += e1 * wv.z; acc[1].w += e1 * wv.w;
            acc[2].x += e2 * wv.x; acc[2].y += e2 * wv.y; acc[2].z += e2 * wv.z; acc[2].w += e2 * wv.w;
            acc[3].x += e3 * wv.x; acc[3].y += e3 * wv.y; acc[3].z += e3 * wv.z; acc[3].w += e3 * wv.w;
        }
#pragma unroll
        for (int e = 0; e < 4; e++) {
            long r = base + e;
            if (r < N) {
                ((float4*)g_v)[r * 32 + l]   = acc[e];
                ((float4*)g_agg)[r * 32 + l] = f4zero();
            }
        }
        __syncwarp();
    }
}

// ---------------------------------------------------------------------------
// K2: mma.sync tf32 edge kernel, 16-edge warp tiles, weights via L1 LDG.
// 256 thr = 8 warps, 2 CTAs/SM target (regs capped 128, smem 512B).
// ---------------------------------------------------------------------------
__global__ void __launch_bounds__(256, 2)
k_edge_mma(const float* __restrict__ ea, const float* __restrict__ ew,
           const float* __restrict__ cf2b, const int* __restrict__ ei,
           int E, int N, int ntiles)
{
    __shared__ float sbias[128];
    const int tid = threadIdx.x;
    if (tid < 128) sbias[tid] = cf2b[tid];
    __syncthreads();

    const int wid = tid >> 5;
    const int lane = tid & 31;
    const int rg = lane >> 2;          // row group 0..7
    const int q = lane & 3;            // quad position
    const int odd = q & 1;
    const int srcA = (lane & ~3) | (q >> 1);
    const int srcB = srcA + 2;
    const int boff = q * 16 + rg * 2;  // b-frag ldg.64 offset within 64-u32 block

    const long wstride = (long)gridDim.x * 8;

    for (long tile = (long)blockIdx.x * 8 + wid; tile < ntiles; tile += wstride) {
        const long tb = tile * 16;
        const long r0 = tb + rg;       // this thread's two edge rows
        const long r1 = r0 + 8;
        const bool in0 = r0 < E, in1 = r1 < E;

        // ================= stage 1: C1 = EA[16,64] @ W1 =================
        float c1[16][4];
#pragma unroll
        for (int nt = 0; nt < 16; nt++)
#pragma unroll
            for (int i = 0; i < 4; i++) c1[nt][i] = 0.f;

#pragma unroll
        for (int kt = 0; kt < 8; kt++) {
            uint32_t a[4];
            const float* p0 = ea + r0 * 64 + kt * 8 + q;
            const float* p1 = ea + r1 * 64 + kt * 8 + q;
            a[0] = cvt_tf32(in0 ? __ldg(p0)     : 0.f);
            a[1] = cvt_tf32(in1 ? __ldg(p1)     : 0.f);
            a[2] = cvt_tf32(in0 ? __ldg(p0 + 4) : 0.f);
            a[3] = cvt_tf32(in1 ? __ldg(p1 + 4) : 0.f);
#pragma unroll
            for (int nt = 0; nt < 16; nt++) {
                uint2 bb = __ldg((const uint2*)(g_w1p + (kt * 16 + nt) * 64 + boff));
                mma_tf32(c1[nt], a, bb.x, bb.y);
            }
        }

        // h1 = ssp(C1) as tf32 bits (kept as floats for shuffling)
#pragma unroll
        for (int nt = 0; nt < 16; nt++)
#pragma unroll
            for (int i = 0; i < 4; i++)
                c1[nt][i] = __uint_as_float(cvt_tf32(sspf(c1[nt][i])));

        // edge metadata (hoisted out of nh loop)
        bool v0 = in0, v1 = in1;
        int s0 = 0, d0 = 0, s1 = 0, d1 = 0;
        float w0 = 0.f, w1 = 0.f;
        if (v0) {
            s0 = ei[r0]; d0 = ei[E + r0]; w0 = ew[r0];
            if ((unsigned)s0 >= (unsigned)N || (unsigned)d0 >= (unsigned)N) v0 = false;
        }
        if (v1) {
            s1 = ei[r1]; d1 = ei[E + r1]; w1 = ew[r1];
            if ((unsigned)s1 >= (unsigned)N || (unsigned)d1 >= (unsigned)N) v1 = false;
        }

        // ============== stage 2: C2 = h1[16,128] @ W2, n-halves ==============
#pragma unroll
        for (int nh = 0; nh < 2; nh++) {
            float c2[8][4];
#pragma unroll
            for (int nt = 0; nt < 8; nt++)
#pragma unroll
                for (int i = 0; i < 4; i++) c2[nt][i] = 0.f;

#pragma unroll
            for (int kt = 0; kt < 16; kt++) {
                uint32_t a[4];
                // C(m16n8) frag -> A(m16k8) frag: quad permutation
                a[0] = __float_as_uint(quad_pick(c1[kt][0], c1[kt][1], srcA, odd));
                a[1] = __float_as_uint(quad_pick(c1[kt][2], c1[kt][3], srcA, odd));
                a[2] = __float_as_uint(quad_pick(c1[kt][0], c1[kt][1], srcB, odd));
                a[3] = __float_as_uint(quad_pick(c1[kt][2], c1[kt][3], srcB, odd));
#pragma unroll
                for (int nt = 0; nt < 8; nt++) {
                    uint2 bb = __ldg((const uint2*)(g_w2p + (kt * 16 + nh * 8 + nt) * 64 + boff));
                    mma_tf32(c2[nt], a, bb.x, bb.y);
                }
            }

            // ---- epilogue: h2 = ssp(C2+bias); msg = v[src]*h2*ew -> red ----
#pragma unroll
            for (int nt = 0; nt < 8; nt++) {
                int cn = nh * 64 + nt * 8 + 2 * q;
                float bf0 = sbias[cn], bf1 = sbias[cn + 1];
                if (v0) {
                    float h0 = sspf(c2[nt][0] + bf0);
                    float h1 = sspf(c2[nt][1] + bf1);
                    float2 vv = *(const float2*)&g_v[(long)s0 * 128 + cn];
                    red2(&g_agg[(long)d0 * 128 + cn], vv.x * h0 * w0, vv.y * h1 * w0);
                }
                if (v1) {
                    float h0 = sspf(c2[nt][2] + bf0);
                    float h1 = sspf(c2[nt][3] + bf1);
                    float2 vv = *(const float2*)&g_v[(long)s1 * 128 + cn];
                    red2(&g_agg[(long)d1 * 128 + cn], vv.x * h0 * w1, vv.y * h1 * w1);
                }
            }
        }
    }
}

// ---------------------------------------------------------------------------
// K3: post MLP + residual (R3-passing version, unchanged)
// ---------------------------------------------------------------------------
__global__ void __launch_bounds__(TPB, 1)
k_post(const float* __restrict__ x,
       const float* __restrict__ w2, const float* __restrict__ b2,
       const float* __restrict__ w3, const float* __restrict__ b3,
       float* __restrict__ out, int N)
{
    extern __shared__ float sm[];
    float* sw2 = sm;
    float* sw3 = sw2 + 128 * 128;
    float* sb2 = sw3 + 128 * 128;
    float* sb3 = sb2 + 128;
    float* st  = sb3 + 128;

    for (int i = threadIdx.x; i < 128 * 128 / 4; i += TPB) {
        ((float4*)sw2)[i] = ((const float4*)w2)[i];
        ((float4*)sw3)[i] = ((const float4*)w3)[i];
    }
    for (int i = threadIdx.x; i < 32; i += TPB) {
        ((float4*)sb2)[i] = ((const float4*)b2)[i];
        ((float4*)sb3)[i] = ((const float4*)b3)[i];
    }
    __syncthreads();

    const int wid = threadIdx.x >> 5, l = threadIdx.x & 31;
    float* stw = st + wid * 512;
    const long stride = (long)gridDim.x * NW * 4;

    for (long base = (long)(blockIdx.x * NW + wid) * 4; base < N; base += stride) {
        for (int i = l; i < 128; i += 32) {
            int e = i >> 5, qq = i & 31;
            long r = base + e;
            ((float4*)stw)[e * 32 + qq] = (r < N) ? ((const float4*)g_agg)[r * 32 + qq] : f4zero();
        }
        __syncwarp();

        float4 bb2 = ((float4*)sb2)[l];
        float4 a[4] = {bb2, bb2, bb2, bb2};
#pragma unroll 8
        for (int k = 0; k < 128; k++) {
            float4 wv = ((float4*)sw2)[k * 32 + l];
            float e0 = stw[k], e1 = stw[128 + k], e2 = stw[256 + k], e3 = stw[384 + k];
            a[0].x += e0 * wv.x; a[0].y += e0 * wv.y; a[0].z += e0 * wv.z; a[0].w += e0 * wv.w;
            a[1].x += e1 * wv.x; a[1].y += e1 * wv.y; a[1].z += e1 * wv.z; a[1].w += e1 * wv.w;
            a[2].x += e2 * wv.x; a[2].y += e2 * wv.y; a[2].z += e2 * wv.z; a[2].w += e2 * wv.w;
            a[3].x += e3 * wv.x; a[3].y += e3 * wv.y; a[3].z += e3 * wv.z; a[3].w += e3 * wv.w;
        }
        __syncwarp();
#pragma unroll
        for (int e = 0; e < 4; e++)
            ((float4*)stw)[e * 32 + l] = ssp4(a[e]);
        __syncwarp();

        float4 bb3 = ((float4*)sb3)[l];
        float4 c[4] = {bb3, bb3, bb3, bb3};
#pragma unroll 8
        for (int k = 0; k < 128; k++) {
            float4 wv = ((float4*)sw3)[k * 32 + l];
            float e0 = stw[k], e1 = stw[128 + k], e2 = stw[256 + k], e3 = stw[384 + k];
            c[0].x += e0 * wv.x; c[0].y += e0 * wv.y; c[0].z += e0 * wv.z; c[0].w += e0 * wv.w;
            c[1].x += e1 * wv.x; c[1].y += e1 * wv.y; c[1].z += e1 * wv.z; c[1].w += e1 * wv.w;
            c[2].x += e2 * wv.x; c[2].y += e2 * wv.y; c[2].z += e2 * wv.z; c[2].w += e2 * wv.w;
            c[3].x += e3 * wv.x; c[3].y += e3 * wv.y; c[3].z += e3 * wv.z; c[3].w += e3 * wv.w;
        }
#pragma unroll
        for (int e = 0; e < 4; e++) {
            long r = base + e;
            if (r < N) {
                float4 xv = ((const float4*)x)[r * 32 + l];
                ((float4*)out)[r * 32 + l] =
                    make_float4(xv.x + c[e].x, xv.y + c[e].y, xv.z + c[e].z, xv.w + c[e].w);
            }
        }
        __syncwarp();
    }
}

// ---------------------------------------------------------------------------

static const int SMEM1 = (128 * 128 + 128 + NW * 4 * 128) * 4;
static const int SMEM3 = (2 * 128 * 128 + 256 + NW * 4 * 128) * 4;

extern "C" void kernel_launch(void* const* d_in, const int* in_sizes, int n_in,
                              void* d_out, int out_size)
{
    const float* x    = (const float*)d_in[0];
    const float* ea   = (const float*)d_in[1];
    const float* ew   = (const float*)d_in[2];
    const float* l1w  = (const float*)d_in[3];
    const float* l1b  = (const float*)d_in[4];
    const float* cf1  = (const float*)d_in[5];
    const float* cf2  = (const float*)d_in[6];
    const float* cf2b = (const float*)d_in[7];
    const float* l2w  = (const float*)d_in[8];
    const float* l2b  = (const float*)d_in[9];
    const float* l3w  = (const float*)d_in[10];
    const float* l3b  = (const float*)d_in[11];
    const int*   ei   = (const int*)d_in[12];

    int N = in_sizes[0] / 128;
    int E = in_sizes[1] / 64;
    int ntiles = (E + 15) / 16;

    cudaFuncSetAttribute(k_vproj, cudaFuncAttributeMaxDynamicSharedMemorySize, SMEM1);
    cudaFuncSetAttribute(k_post,  cudaFuncAttributeMaxDynamicSharedMemorySize, SMEM3);

    k_wprep   <<<64, 256>>>(cf1, cf2);
    k_vproj   <<<GRID, TPB, SMEM1>>>(x, l1w, l1b, N);
    k_edge_mma<<<296, 256>>>(ea, ew, cf2b, ei, E, N, ntiles);
    k_post    <<<GRID, TPB, SMEM3>>>(x, l2w, l2b, l3w, l3b, (float*)d_out, N);
}

// round 14
// speedup vs baseline: 2.7734x; 1.7151x over previous
#include <cuda_runtime.h>
#include <cstdint>

// ---------------------------------------------------------------------------
// SchNet interaction block.
//   K0: pre-permute cf1/cf2 into bf16-pair global scratch (b-frag = ldg.64)
//   K1: v = x@lin1_w + lin1_b ; zero g_agg            (fp32 FFMA)
//   K2: edge filter net via mma.sync m16n8k16 bf16 + gather/modulate/scatter
//       zero shuffles: packed C1 pairs ARE stage-2 A-frags lane-locally
//   K3: out = x + ssp(agg@lin2_w+b2)@lin3_w + b3      (fp32 FFMA)
// Base-target sm_103: mma.sync only. edge_index = int32 (verified R3).
// R13 bug fixed: B-blocks are 64 u32 (32 lanes x 2 regs), not 32.
// ---------------------------------------------------------------------------

#define NW   16
#define TPB  (NW * 32)
#define GRID 152

#define N_NODES 100000
#define H 128

#define W1B   (4 * 16 * 64)     // 4096 u32 (k=64 -> 4 kt16 blocks x 16 nt x 64)
#define W2B   (8 * 16 * 64)     // 8192 u32 (k=128 -> 8 kt16 blocks x 16 nt x 64)

__device__ __align__(128) float g_v[N_NODES * H];
__device__ __align__(128) float g_agg[N_NODES * H];
__device__ __align__(128) uint32_t g_w1b[W1B];
__device__ __align__(128) uint32_t g_w2b[W2B];

#define LN2F 0.69314718055994530942f
#define L2EF 1.44269504088896340736f

__device__ __forceinline__ float ex2f(float x) {
    float r; asm("ex2.approx.f32 %0, %1;" : "=f"(r) : "f"(x)); return r;
}
__device__ __forceinline__ float lg2f(float x) {
    float r; asm("lg2.approx.f32 %0, %1;" : "=f"(r) : "f"(x)); return r;
}
__device__ __forceinline__ float sspf(float z) {
    float t = ex2f(-fabsf(z) * L2EF);
    float u = lg2f(1.0f + t);
    return fmaxf(z, 0.0f) + fmaf(u, LN2F, -LN2F);
}
__device__ __forceinline__ float4 ssp4(float4 a) {
    return make_float4(sspf(a.x), sspf(a.y), sspf(a.z), sspf(a.w));
}
__device__ __forceinline__ float4 f4zero() { return make_float4(0.f, 0.f, 0.f, 0.f); }

// pack two fp32 -> bf16x2 (lo = even-k element, hi = odd-k element)
__device__ __forceinline__ uint32_t pack_bf2(float lo, float hi) {
    uint32_t r; asm("cvt.rn.bf16x2.f32 %0, %1, %2;" : "=r"(r) : "f"(hi), "f"(lo));
    return r;
}
__device__ __forceinline__ void mma_bf16(float c[4], uint32_t a0, uint32_t a1,
                                         uint32_t a2, uint32_t a3,
                                         uint32_t b0, uint32_t b1) {
    asm volatile("mma.sync.aligned.m16n8k16.row.col.f32.bf16.bf16.f32 "
                 "{%0,%1,%2,%3}, {%4,%5,%6,%7}, {%8,%9}, {%0,%1,%2,%3};"
                 : "+f"(c[0]), "+f"(c[1]), "+f"(c[2]), "+f"(c[3])
                 : "r"(a0), "r"(a1), "r"(a2), "r"(a3), "r"(b0), "r"(b1));
}
__device__ __forceinline__ void red2(float* p, float m0, float m1) {
    asm volatile("red.global.add.v2.f32 [%0], {%1, %2};"
                 :: "l"(p), "f"(m0), "f"(m1) : "memory");
}

// ---------------------------------------------------------------------------
// K0: weight prep -> bf16 pairs, 64-u32 block per (kt16, nt8):
//   j = lane*2 + reg (j in 0..63, lane 0..31); lane = (rg_b<<2)|q_b
//   b_reg: k = kt*16 + 2*q_b + reg*8 (+1 in hi), n = nt*8 + rg_b
// Warp b-frag fetch = one coalesced 256B ldg.64 sweep.
// ---------------------------------------------------------------------------
__global__ void k_wprep(const float* __restrict__ cf1, const float* __restrict__ cf2)
{
    int stride = blockDim.x * gridDim.x;
    for (int f = blockIdx.x * blockDim.x + threadIdx.x; f < W1B; f += stride) {
        int block = f >> 6, j = f & 63;
        int kt = block >> 4, nt = block & 15;
        int lane = j >> 1, reg = j & 1;
        int rgb = lane >> 2, qb = lane & 3;
        int k = kt * 16 + 2 * qb + reg * 8;
        int n = nt * 8 + rgb;
        g_w1b[f] = pack_bf2(cf1[k * 128 + n], cf1[(k + 1) * 128 + n]);
    }
    for (int f = blockIdx.x * blockDim.x + threadIdx.x; f < W2B; f += stride) {
        int block = f >> 6, j = f & 63;
        int kt = block >> 4, nt = block & 15;
        int lane = j >> 1, reg = j & 1;
        int rgb = lane >> 2, qb = lane & 3;
        int k = kt * 16 + 2 * qb + reg * 8;
        int n = nt * 8 + rgb;
        g_w2b[f] = pack_bf2(cf2[k * 128 + n], cf2[(k + 1) * 128 + n]);
    }
}

// ---------------------------------------------------------------------------
// K1: node projection (R3-passing version, unchanged)
// ---------------------------------------------------------------------------
__global__ void __launch_bounds__(TPB, 1)
k_vproj(const float* __restrict__ x, const float* __restrict__ w,
        const float* __restrict__ b, int N)
{
    extern __shared__ float sm[];
    float* sw = sm;
    float* sb = sw + 128 * 128;
    float* sx = sb + 128;

    for (int i = threadIdx.x; i < 128 * 128 / 4; i += TPB)
        ((float4*)sw)[i] = ((const float4*)w)[i];
    for (int i = threadIdx.x; i < 32; i += TPB)
        ((float4*)sb)[i] = ((const float4*)b)[i];
    __syncthreads();

    const int wid = threadIdx.x >> 5, l = threadIdx.x & 31;
    float* sxw = sx + wid * 4 * 128;
    const long stride = (long)gridDim.x * NW * 4;

    for (long base = (long)(blockIdx.x * NW + wid) * 4; base < N; base += stride) {
        for (int i = l; i < 128; i += 32) {
            int e = i >> 5, q = i & 31;
            long r = base + e;
            ((float4*)sxw)[e * 32 + q] = (r < N) ? ((const float4*)x)[r * 32 + q] : f4zero();
        }
        __syncwarp();

        float4 bb = ((float4*)sb)[l];
        float4 acc[4] = {bb, bb, bb, bb};
#pragma unroll 8
        for (int k = 0; k < 128; k++) {
            float4 wv = ((float4*)sw)[k * 32 + l];
            float e0 = sxw[k], e1 = sxw[128 + k], e2 = sxw[256 + k], e3 = sxw[384 + k];
            acc[0].x += e0 * wv.x; acc[0].y += e0 * wv.y; acc[0].z += e0 * wv.z; acc[0].w += e0 * wv.w;
            acc[1].x += e1 * wv.x; acc[1].y += e1 * wv.y; acc[1].z += e1 * wv.z; acc[1].w += e1 * wv.w;
            acc[2].x += e2 * wv.x; acc[2].y += e2 * wv.y; acc[2].z += e2 * wv.z; acc[2].w += e2 * wv.w;
            acc[3].x += e3 * wv.x; acc[3].y += e3 * wv.y; acc[3].z += e3 * wv.z; acc[3].w += e3 * wv.w;
        }
#pragma unroll
        for (int e = 0; e < 4; e++) {
            long r = base + e;
            if (r < N) {
                ((float4*)g_v)[r * 32 + l]   = acc[e];
                ((float4*)g_agg)[r * 32 + l] = f4zero();
            }
        }
        __syncwarp();
    }
}

// ---------------------------------------------------------------------------
// K2: bf16 mma edge kernel. 16-edge warp tiles, no shuffles, no spills.
// ---------------------------------------------------------------------------
__global__ void __launch_bounds__(256, 2)
k_edge_mma(const float* __restrict__ ea, const float* __restrict__ ew,
           const float* __restrict__ cf2b, const int* __restrict__ ei,
           int E, int N, int ntiles)
{
    __shared__ float sbias[128];
    const int tid = threadIdx.x;
    if (tid < 128) sbias[tid] = cf2b[tid];
    __syncthreads();

    const int wid = tid >> 5;
    const int lane = tid & 31;
    const int rg = lane >> 2;          // row group 0..7
    const int q = lane & 3;            // quad position
    const int boff2 = lane * 2;        // b-frag u32 offset within 64-u32 block

    const long wstride = (long)gridDim.x * 8;

    for (long tile = (long)blockIdx.x * 8 + wid; tile < ntiles; tile += wstride) {
        const long tb = tile * 16;
        const long r0 = tb + rg;       // this thread's two edge rows
        const long r1 = r0 + 8;
        const bool in0 = r0 < E, in1 = r1 < E;

        // ================= stage 1: C1 = EA[16,64] @ W1 (4 kt16 steps) =====
        float c1[16][4];
#pragma unroll
        for (int nt = 0; nt < 16; nt++)
#pragma unroll
            for (int i = 0; i < 4; i++) c1[nt][i] = 0.f;

#pragma unroll
        for (int kt = 0; kt < 4; kt++) {
            int cb = kt * 16 + 2 * q;
            float2 f0 = in0 ? __ldg((const float2*)(ea + r0 * 64 + cb))     : make_float2(0.f, 0.f);
            float2 f1 = in1 ? __ldg((const float2*)(ea + r1 * 64 + cb))     : make_float2(0.f, 0.f);
            float2 f2 = in0 ? __ldg((const float2*)(ea + r0 * 64 + cb + 8)) : make_float2(0.f, 0.f);
            float2 f3 = in1 ? __ldg((const float2*)(ea + r1 * 64 + cb + 8)) : make_float2(0.f, 0.f);
            uint32_t a0 = pack_bf2(f0.x, f0.y);
            uint32_t a1 = pack_bf2(f1.x, f1.y);
            uint32_t a2 = pack_bf2(f2.x, f2.y);
            uint32_t a3 = pack_bf2(f3.x, f3.y);
#pragma unroll
            for (int nt = 0; nt < 16; nt++) {
                uint2 bb = __ldg((const uint2*)(g_w1b + (kt * 16 + nt) * 64 + boff2));
                mma_bf16(c1[nt], a0, a1, a2, a3, bb.x, bb.y);
            }
        }

        // h1 = ssp(C1) packed to bf16 pairs — these ARE stage-2 A-frag regs.
        uint32_t p_lo[16], p_hi[16];
#pragma unroll
        for (int nt = 0; nt < 16; nt++) {
            p_lo[nt] = pack_bf2(sspf(c1[nt][0]), sspf(c1[nt][1]));
            p_hi[nt] = pack_bf2(sspf(c1[nt][2]), sspf(c1[nt][3]));
        }

        // edge metadata
        bool v0 = in0, v1 = in1;
        int s0 = 0, d0 = 0, s1 = 0, d1 = 0;
        float w0 = 0.f, w1 = 0.f;
        if (v0) {
            s0 = ei[r0]; d0 = ei[E + r0]; w0 = ew[r0];
            if ((unsigned)s0 >= (unsigned)N || (unsigned)d0 >= (unsigned)N) v0 = false;
        }
        if (v1) {
            s1 = ei[r1]; d1 = ei[E + r1]; w1 = ew[r1];
            if ((unsigned)s1 >= (unsigned)N || (unsigned)d1 >= (unsigned)N) v1 = false;
        }

        // ========== stage 2: C2 = h1[16,128] @ W2 (8 kt16), n-halves ==========
#pragma unroll
        for (int nh = 0; nh < 2; nh++) {
            float c2[8][4];
#pragma unroll
            for (int nt = 0; nt < 8; nt++)
#pragma unroll
                for (int i = 0; i < 4; i++) c2[nt][i] = 0.f;

#pragma unroll
            for (int kt = 0; kt < 8; kt++) {
                uint32_t a0 = p_lo[2 * kt],     a1 = p_hi[2 * kt];
                uint32_t a2 = p_lo[2 * kt + 1], a3 = p_hi[2 * kt + 1];
#pragma unroll
                for (int nt = 0; nt < 8; nt++) {
                    uint2 bb = __ldg((const uint2*)(g_w2b + (kt * 16 + nh * 8 + nt) * 64 + boff2));
                    mma_bf16(c2[nt], a0, a1, a2, a3, bb.x, bb.y);
                }
            }

            // ---- epilogue: h2 = ssp(C2+bias); msg = v[src]*h2*ew -> red ----
#pragma unroll
            for (int nt = 0; nt < 8; nt++) {
                int cn = nh * 64 + nt * 8 + 2 * q;
                float bf0 = sbias[cn], bf1 = sbias[cn + 1];
                if (v0) {
                    float h0 = sspf(c2[nt][0] + bf0);
                    float h1 = sspf(c2[nt][1] + bf1);
                    float2 vv = *(const float2*)&g_v[(long)s0 * 128 + cn];
                    red2(&g_agg[(long)d0 * 128 + cn], vv.x * h0 * w0, vv.y * h1 * w0);
                }
                if (v1) {
                    float h0 = sspf(c2[nt][2] + bf0);
                    float h1 = sspf(c2[nt][3] + bf1);
                    float2 vv = *(const float2*)&g_v[(long)s1 * 128 + cn];
                    red2(&g_agg[(long)d1 * 128 + cn], vv.x * h0 * w1, vv.y * h1 * w1);
                }
            }
        }
    }
}

// ---------------------------------------------------------------------------
// K3: post MLP + residual (R3-passing version, unchanged)
// ---------------------------------------------------------------------------
__global__ void __launch_bounds__(TPB, 1)
k_post(const float* __restrict__ x,
       const float* __restrict__ w2, const float* __restrict__ b2,
       const float* __restrict__ w3, const float* __restrict__ b3,
       float* __restrict__ out, int N)
{
    extern __shared__ float sm[];
    float* sw2 = sm;
    float* sw3 = sw2 + 128 * 128;
    float* sb2 = sw3 + 128 * 128;
    float* sb3 = sb2 + 128;
    float* st  = sb3 + 128;

    for (int i = threadIdx.x; i < 128 * 128 / 4; i += TPB) {
        ((float4*)sw2)[i] = ((const float4*)w2)[i];
        ((float4*)sw3)[i] = ((const float4*)w3)[i];
    }
    for (int i = threadIdx.x; i < 32; i += TPB) {
        ((float4*)sb2)[i] = ((const float4*)b2)[i];
        ((float4*)sb3)[i] = ((const float4*)b3)[i];
    }
    __syncthreads();

    const int wid = threadIdx.x >> 5, l = threadIdx.x & 31;
    float* stw = st + wid * 512;
    const long stride = (long)gridDim.x * NW * 4;

    for (long base = (long)(blockIdx.x * NW + wid) * 4; base < N; base += stride) {
        for (int i = l; i < 128; i += 32) {
            int e = i >> 5, qq = i & 31;
            long r = base + e;
            ((float4*)stw)[e * 32 + qq] = (r < N) ? ((const float4*)g_agg)[r * 32 + qq] : f4zero();
        }
        __syncwarp();

        float4 bb2 = ((float4*)sb2)[l];
        float4 a[4] = {bb2, bb2, bb2, bb2};
#pragma unroll 8
        for (int k = 0; k < 128; k++) {
            float4 wv = ((float4*)sw2)[k * 32 + l];
            float e0 = stw[k], e1 = stw[128 + k], e2 = stw[256 + k], e3 = stw[384 + k];
            a[0].x += e0 * wv.x; a[0].y += e0 * wv.y; a[0].z += e0 * wv.z; a[0].w += e0 * wv.w;
            a[1].x += e1 * wv.x; a[1].y += e1 * wv.y; a[1].z += e1 * wv.z; a[1].w += e1 * wv.w;
            a[2].x += e2 * wv.x; a[2].y += e2 * wv.y; a[2].z += e2 * wv.z; a[2].w += e2 * wv.w;
            a[3].x += e3 * wv.x; a[3].y += e3 * wv.y; a[3].z += e3 * wv.z; a[3].w += e3 * wv.w;
        }
        __syncwarp();
#pragma unroll
        for (int e = 0; e < 4; e++)
            ((float4*)stw)[e * 32 + l] = ssp4(a[e]);
        __syncwarp();

        float4 bb3 = ((float4*)sb3)[l];
        float4 c[4] = {bb3, bb3, bb3, bb3};
#pragma unroll 8
        for (int k = 0; k < 128; k++) {
            float4 wv = ((float4*)sw3)[k * 32 + l];
            float e0 = stw[k], e1 = stw[128 + k], e2 = stw[256 + k], e3 = stw[384 + k];
            c[0].x += e0 * wv.x; c[0].y += e0 * wv.y; c[0].z += e0 * wv.z; c[0].w += e0 * wv.w;
            c[1].x += e1 * wv.x; c[1].y += e1 * wv.y; c[1].z += e1 * wv.z; c[1].w += e1 * wv.w;
            c[2].x += e2 * wv.x; c[2].y += e2 * wv.y; c[2].z += e2 * wv.z; c[2].w += e2 * wv.w;
            c[3].x += e3 * wv.x; c[3].y += e3 * wv.y; c[3].z += e3 * wv.z; c[3].w += e3 * wv.w;
        }
#pragma unroll
        for (int e = 0; e < 4; e++) {
            long r = base + e;
            if (r < N) {
                float4 xv = ((const float4*)x)[r * 32 + l];
                ((float4*)out)[r * 32 + l] =
                    make_float4(xv.x + c[e].x, xv.y + c[e].y, xv.z + c[e].z, xv.w + c[e].w);
            }
        }
        __syncwarp();
    }
}

// ---------------------------------------------------------------------------

static const int SMEM1 = (128 * 128 + 128 + NW * 4 * 128) * 4;
static const int SMEM3 = (2 * 128 * 128 + 256 + NW * 4 * 128) * 4;

extern "C" void kernel_launch(void* const* d_in, const int* in_sizes, int n_in,
                              void* d_out, int out_size)
{
    const float* x    = (const float*)d_in[0];
    const float* ea   = (const float*)d_in[1];
    const float* ew   = (const float*)d_in[2];
    const float* l1w  = (const float*)d_in[3];
    const float* l1b  = (const float*)d_in[4];
    const float* cf1  = (const float*)d_in[5];
    const float* cf2  = (const float*)d_in[6];
    const float* cf2b = (const float*)d_in[7];
    const float* l2w  = (const float*)d_in[8];
    const float* l2b  = (const float*)d_in[9];
    const float* l3w  = (const float*)d_in[10];
    const float* l3b  = (const float*)d_in[11];
    const int*   ei   = (const int*)d_in[12];

    int N = in_sizes[0] / 128;
    int E = in_sizes[1] / 64;
    int ntiles = (E + 15) / 16;

    cudaFuncSetAttribute(k_vproj, cudaFuncAttributeMaxDynamicSharedMemorySize, SMEM1);
    cudaFuncSetAttribute(k_post,  cudaFuncAttributeMaxDynamicSharedMemorySize, SMEM3);

    k_wprep   <<<48, 256>>>(cf1, cf2);
    k_vproj   <<<GRID, TPB, SMEM1>>>(x, l1w, l1b, N);
    k_edge_mma<<<296, 256>>>(ea, ew, cf2b, ei, E, N, ntiles);
    k_post    <<<GRID, TPB, SMEM3>>>(x, l2w, l2b, l3w, l3b, (float*)d_out, N);
}

// round 15
// speedup vs baseline: 3.8944x; 1.4042x over previous
#include <cuda_runtime.h>
#include <cstdint>

// ---------------------------------------------------------------------------
// SchNet interaction block.
//   K0: pre-permute cf1/cf2/lin2/lin3 into bf16-pair global scratch
//   K1: v = x@lin1_w + lin1_b ; zero g_agg            (fp32 FFMA)
//   K2: edge filter net via mma.sync m16n8k16 bf16; stage-2 output columns
//       permuted (Lcol) so each thread owns 4 consecutive cols -> red.v4
//   K3: out = x + ssp(agg@lin2+b2)@lin3 + b3 via the same bf16 mma scheme
// Base-target sm_103: mma.sync only. edge_index = int32 (verified R3).
// ---------------------------------------------------------------------------

#define NW   16
#define TPB  (NW * 32)
#define GRID 152

#define N_NODES 100000
#define H 128

#define W1B   (4 * 16 * 64)     // ea->h1 weights   (k=64)
#define W2B   (8 * 16 * 64)     // h1->h2 weights   (k=128)
#define WL2   (8 * 16 * 64)     // agg->t  weights  (k=128)
#define WL3   (8 * 16 * 64)     // t->out  weights  (k=128)

__device__ __align__(128) float g_v[N_NODES * H];
__device__ __align__(128) float g_agg[N_NODES * H];
__device__ __align__(128) uint32_t g_w1b[W1B];
__device__ __align__(128) uint32_t g_w2b[W2B];
__device__ __align__(128) uint32_t g_wl2[WL2];
__device__ __align__(128) uint32_t g_wl3[WL3];

#define LN2F 0.69314718055994530942f
#define L2EF 1.44269504088896340736f

__device__ __forceinline__ float ex2f(float x) {
    float r; asm("ex2.approx.f32 %0, %1;" : "=f"(r) : "f"(x)); return r;
}
__device__ __forceinline__ float lg2f(float x) {
    float r; asm("lg2.approx.f32 %0, %1;" : "=f"(r) : "f"(x)); return r;
}
__device__ __forceinline__ float sspf(float z) {
    float t = ex2f(-fabsf(z) * L2EF);
    float u = lg2f(1.0f + t);
    return fmaxf(z, 0.0f) + fmaf(u, LN2F, -LN2F);
}
__device__ __forceinline__ float4 ssp4(float4 a) {
    return make_float4(sspf(a.x), sspf(a.y), sspf(a.z), sspf(a.w));
}
__device__ __forceinline__ float4 f4zero() { return make_float4(0.f, 0.f, 0.f, 0.f); }

__device__ __forceinline__ uint32_t pack_bf2(float lo, float hi) {
    uint32_t r; asm("cvt.rn.bf16x2.f32 %0, %1, %2;" : "=r"(r) : "f"(hi), "f"(lo));
    return r;
}
__device__ __forceinline__ void mma_bf16(float c[4], uint32_t a0, uint32_t a1,
                                         uint32_t a2, uint32_t a3,
                                         uint32_t b0, uint32_t b1) {
    asm volatile("mma.sync.aligned.m16n8k16.row.col.f32.bf16.bf16.f32 "
                 "{%0,%1,%2,%3}, {%4,%5,%6,%7}, {%8,%9}, {%0,%1,%2,%3};"
                 : "+f"(c[0]), "+f"(c[1]), "+f"(c[2]), "+f"(c[3])
                 : "r"(a0), "r"(a1), "r"(a2), "r"(a3), "r"(b0), "r"(b1));
}
__device__ __forceinline__ void red4(float* p, float m0, float m1, float m2, float m3) {
    asm volatile("red.global.add.v4.f32 [%0], {%1, %2, %3, %4};"
                 :: "l"(p), "f"(m0), "f"(m1), "f"(m2), "f"(m3) : "memory");
}

// Lcol: output-column permutation pairing adjacent n8 blocks so thread q owns
// 4 consecutive logical cols: Lcol(nt, n) = 16*(nt>>1) + 4*(n>>1) + 2*(nt&1) + (n&1)
__device__ __forceinline__ int Lcol(int nt, int n) {
    return 16 * (nt >> 1) + 4 * (n >> 1) + 2 * (nt & 1) + (n & 1);
}

// ---------------------------------------------------------------------------
// K0: weight prep. 64-u32 block per (kt16, nt8): j = lane*2+reg,
// lane=(rg_b<<2)|q_b, k = kt*16 + 2*q_b + reg*8 (+1 in hi), n position rg_b.
// g_w1b, g_wl2: n raw (their outputs feed stage-2 k raw). g_w2b, g_wl3: n
// permuted by Lcol (their outputs hit the float4 epilogue).
// ---------------------------------------------------------------------------
__global__ void k_wprep(const float* __restrict__ cf1, const float* __restrict__ cf2,
                        const float* __restrict__ l2w, const float* __restrict__ l3w)
{
    int stride = blockDim.x * gridDim.x;
    int t0 = blockIdx.x * blockDim.x + threadIdx.x;
    for (int f = t0; f < W1B; f += stride) {
        int block = f >> 6, j = f & 63;
        int kt = block >> 4, nt = block & 15;
        int lane = j >> 1, reg = j & 1;
        int k = kt * 16 + 2 * (lane & 3) + reg * 8;
        int n = nt * 8 + (lane >> 2);
        g_w1b[f] = pack_bf2(cf1[k * 128 + n], cf1[(k + 1) * 128 + n]);
    }
    for (int f = t0; f < W2B; f += stride) {
        int block = f >> 6, j = f & 63;
        int kt = block >> 4, nt = block & 15;
        int lane = j >> 1, reg = j & 1;
        int k = kt * 16 + 2 * (lane & 3) + reg * 8;
        int n = Lcol(nt, lane >> 2);   // permuted output cols
        g_w2b[f] = pack_bf2(cf2[k * 128 + n], cf2[(k + 1) * 128 + n]);
    }
    for (int f = t0; f < WL2; f += stride) {
        int block = f >> 6, j = f & 63;
        int kt = block >> 4, nt = block & 15;
        int lane = j >> 1, reg = j & 1;
        int k = kt * 16 + 2 * (lane & 3) + reg * 8;
        int n = nt * 8 + (lane >> 2);
        g_wl2[f] = pack_bf2(l2w[k * 128 + n], l2w[(k + 1) * 128 + n]);
    }
    for (int f = t0; f < WL3; f += stride) {
        int block = f >> 6, j = f & 63;
        int kt = block >> 4, nt = block & 15;
        int lane = j >> 1, reg = j & 1;
        int k = kt * 16 + 2 * (lane & 3) + reg * 8;
        int n = Lcol(nt, lane >> 2);   // permuted output cols
        g_wl3[f] = pack_bf2(l3w[k * 128 + n], l3w[(k + 1) * 128 + n]);
    }
}

// ---------------------------------------------------------------------------
// K1: node projection (unchanged)
// ---------------------------------------------------------------------------
__global__ void __launch_bounds__(TPB, 1)
k_vproj(const float* __restrict__ x, const float* __restrict__ w,
        const float* __restrict__ b, int N)
{
    extern __shared__ float sm[];
    float* sw = sm;
    float* sb = sw + 128 * 128;
    float* sx = sb + 128;

    for (int i = threadIdx.x; i < 128 * 128 / 4; i += TPB)
        ((float4*)sw)[i] = ((const float4*)w)[i];
    for (int i = threadIdx.x; i < 32; i += TPB)
        ((float4*)sb)[i] = ((const float4*)b)[i];
    __syncthreads();

    const int wid = threadIdx.x >> 5, l = threadIdx.x & 31;
    float* sxw = sx + wid * 4 * 128;
    const long stride = (long)gridDim.x * NW * 4;

    for (long base = (long)(blockIdx.x * NW + wid) * 4; base < N; base += stride) {
        for (int i = l; i < 128; i += 32) {
            int e = i >> 5, q = i & 31;
            long r = base + e;
            ((float4*)sxw)[e * 32 + q] = (r < N) ? ((const float4*)x)[r * 32 + q] : f4zero();
        }
        __syncwarp();

        float4 bb = ((float4*)sb)[l];
        float4 acc[4] = {bb, bb, bb, bb};
#pragma unroll 8
        for (int k = 0; k < 128; k++) {
            float4 wv = ((float4*)sw)[k * 32 + l];
            float e0 = sxw[k], e1 = sxw[128 + k], e2 = sxw[256 + k], e3 = sxw[384 + k];
            acc[0].x += e0 * wv.x; acc[0].y += e0 * wv.y; acc[0].z += e0 * wv.z; acc[0].w += e0 * wv.w;
            acc[1].x += e1 * wv.x; acc[1].y += e1 * wv.y; acc[1].z += e1 * wv.z; acc[1].w += e1 * wv.w;
            acc[2].x += e2 * wv.x; acc[2].y += e2 * wv.y; acc[2].z += e2 * wv.z; acc[2].w += e2 * wv.w;
            acc[3].x += e3 * wv.x; acc[3].y += e3 * wv.y; acc[3].z += e3 * wv.z; acc[3].w += e3 * wv.w;
        }
#pragma unroll
        for (int e = 0; e < 4; e++) {
            long r = base + e;
            if (r < N) {
                ((float4*)g_v)[r * 32 + l]   = acc[e];
                ((float4*)g_agg)[r * 32 + l] = f4zero();
            }
        }
        __syncwarp();
    }
}

// ---------------------------------------------------------------------------
// K2: bf16 mma edge kernel. float4 epilogue via Lcol-permuted W2.
// ---------------------------------------------------------------------------
__global__ void __launch_bounds__(256, 2)
k_edge_mma(const float* __restrict__ ea, const float* __restrict__ ew,
           const float* __restrict__ cf2b, const int* __restrict__ ei,
           int E, int N, int ntiles)
{
    __shared__ float sbias[128];
    const int tid = threadIdx.x;
    if (tid < 128) sbias[tid] = cf2b[tid];
    __syncthreads();

    const int wid = tid >> 5;
    const int lane = tid & 31;
    const int rg = lane >> 2;
    const int q = lane & 3;
    const int boff2 = lane * 2;

    const long wstride = (long)gridDim.x * 8;

    for (long tile = (long)blockIdx.x * 8 + wid; tile < ntiles; tile += wstride) {
        const long tb = tile * 16;
        const long r0 = tb + rg;
        const long r1 = r0 + 8;
        const bool in0 = r0 < E, in1 = r1 < E;

        // ========== stage 1: C1 = EA[16,64] @ W1 (raw col order) ==========
        float c1[16][4];
#pragma unroll
        for (int nt = 0; nt < 16; nt++)
#pragma unroll
            for (int i = 0; i < 4; i++) c1[nt][i] = 0.f;

#pragma unroll
        for (int kt = 0; kt < 4; kt++) {
            int cb = kt * 16 + 2 * q;
            float2 f0 = in0 ? __ldg((const float2*)(ea + r0 * 64 + cb))     : make_float2(0.f, 0.f);
            float2 f1 = in1 ? __ldg((const float2*)(ea + r1 * 64 + cb))     : make_float2(0.f, 0.f);
            float2 f2 = in0 ? __ldg((const float2*)(ea + r0 * 64 + cb + 8)) : make_float2(0.f, 0.f);
            float2 f3 = in1 ? __ldg((const float2*)(ea + r1 * 64 + cb + 8)) : make_float2(0.f, 0.f);
            uint32_t a0 = pack_bf2(f0.x, f0.y);
            uint32_t a1 = pack_bf2(f1.x, f1.y);
            uint32_t a2 = pack_bf2(f2.x, f2.y);
            uint32_t a3 = pack_bf2(f3.x, f3.y);
#pragma unroll
            for (int nt = 0; nt < 16; nt++) {
                uint2 bb = __ldg((const uint2*)(g_w1b + (kt * 16 + nt) * 64 + boff2));
                mma_bf16(c1[nt], a0, a1, a2, a3, bb.x, bb.y);
            }
        }

        // h1 = ssp(C1) packed — these ARE stage-2 A-frag regs (raw k order).
        uint32_t p_lo[16], p_hi[16];
#pragma unroll
        for (int nt = 0; nt < 16; nt++) {
            p_lo[nt] = pack_bf2(sspf(c1[nt][0]), sspf(c1[nt][1]));
            p_hi[nt] = pack_bf2(sspf(c1[nt][2]), sspf(c1[nt][3]));
        }

        bool v0 = in0, v1 = in1;
        int s0 = 0, d0 = 0, s1 = 0, d1 = 0;
        float w0 = 0.f, w1 = 0.f;
        if (v0) {
            s0 = ei[r0]; d0 = ei[E + r0]; w0 = ew[r0];
            if ((unsigned)s0 >= (unsigned)N || (unsigned)d0 >= (unsigned)N) v0 = false;
        }
        if (v1) {
            s1 = ei[r1]; d1 = ei[E + r1]; w1 = ew[r1];
            if ((unsigned)s1 >= (unsigned)N || (unsigned)d1 >= (unsigned)N) v1 = false;
        }

        // ========== stage 2: C2 = h1 @ W2 (Lcol-permuted n) =================
#pragma unroll
        for (int nh = 0; nh < 2; nh++) {
            float c2[8][4];
#pragma unroll
            for (int nt = 0; nt < 8; nt++)
#pragma unroll
                for (int i = 0; i < 4; i++) c2[nt][i] = 0.f;

#pragma unroll
            for (int kt = 0; kt < 8; kt++) {
                uint32_t a0 = p_lo[2 * kt],     a1 = p_hi[2 * kt];
                uint32_t a2 = p_lo[2 * kt + 1], a3 = p_hi[2 * kt + 1];
#pragma unroll
                for (int nt = 0; nt < 8; nt++) {
                    uint2 bb = __ldg((const uint2*)(g_w2b + (kt * 16 + nh * 8 + nt) * 64 + boff2));
                    mma_bf16(c2[nt], a0, a1, a2, a3, bb.x, bb.y);
                }
            }

            // ---- float4 epilogue: thread q owns cols cn..cn+3 ----
#pragma unroll
            for (int th = 0; th < 4; th++) {
                int cn = nh * 64 + th * 16 + 4 * q;
                float4 b4 = *(const float4*)&sbias[cn];
                if (v0) {
                    float h0 = sspf(c2[2*th][0]   + b4.x);
                    float h1 = sspf(c2[2*th][1]   + b4.y);
                    float h2 = sspf(c2[2*th+1][0] + b4.z);
                    float h3 = sspf(c2[2*th+1][1] + b4.w);
                    float4 vv = *(const float4*)&g_v[(long)s0 * 128 + cn];
                    red4(&g_agg[(long)d0 * 128 + cn],
                         vv.x * h0 * w0, vv.y * h1 * w0, vv.z * h2 * w0, vv.w * h3 * w0);
                }
                if (v1) {
                    float h0 = sspf(c2[2*th][2]   + b4.x);
                    float h1 = sspf(c2[2*th][3]   + b4.y);
                    float h2 = sspf(c2[2*th+1][2] + b4.z);
                    float h3 = sspf(c2[2*th+1][3] + b4.w);
                    float4 vv = *(const float4*)&g_v[(long)s1 * 128 + cn];
                    red4(&g_agg[(long)d1 * 128 + cn],
                         vv.x * h0 * w1, vv.y * h1 * w1, vv.z * h2 * w1, vv.w * h3 * w1);
                }
            }
        }
    }
}

// ---------------------------------------------------------------------------
// K3: post MLP + residual via bf16 mma (same machinery; coalesced rows).
// ---------------------------------------------------------------------------
__global__ void __launch_bounds__(256, 2)
k_post_mma(const float* __restrict__ x, const float* __restrict__ b2,
           const float* __restrict__ b3, float* __restrict__ out,
           int N, int ntiles)
{
    __shared__ float sb2[128], sb3[128];
    const int tid = threadIdx.x;
    if (tid < 128) { sb2[tid] = b2[tid]; sb3[tid] = b3[tid]; }
    __syncthreads();

    const int wid = tid >> 5;
    const int lane = tid & 31;
    const int rg = lane >> 2;
    const int q = lane & 3;
    const int boff2 = lane * 2;

    const long wstride = (long)gridDim.x * 8;

    for (long tile = (long)blockIdx.x * 8 + wid; tile < ntiles; tile += wstride) {
        const long tb = tile * 16;
        const long r0 = tb + rg;
        const long r1 = r0 + 8;
        const bool in0 = r0 < N, in1 = r1 < N;

        // ===== stage A: C1 = agg[16,128] @ lin2 (raw n) =====
        float c1[16][4];
#pragma unroll
        for (int nt = 0; nt < 16; nt++)
#pragma unroll
            for (int i = 0; i < 4; i++) c1[nt][i] = 0.f;

#pragma unroll
        for (int kt = 0; kt < 8; kt++) {
            int cb = kt * 16 + 2 * q;
            float2 f0 = in0 ? *(const float2*)&g_agg[r0 * 128 + cb]     : make_float2(0.f, 0.f);
            float2 f1 = in1 ? *(const float2*)&g_agg[r1 * 128 + cb]     : make_float2(0.f, 0.f);
            float2 f2 = in0 ? *(const float2*)&g_agg[r0 * 128 + cb + 8] : make_float2(0.f, 0.f);
            float2 f3 = in1 ? *(const float2*)&g_agg[r1 * 128 + cb + 8] : make_float2(0.f, 0.f);
            uint32_t a0 = pack_bf2(f0.x, f0.y);
            uint32_t a1 = pack_bf2(f1.x, f1.y);
            uint32_t a2 = pack_bf2(f2.x, f2.y);
            uint32_t a3 = pack_bf2(f3.x, f3.y);
#pragma unroll
            for (int nt = 0; nt < 16; nt++) {
                uint2 bb = __ldg((const uint2*)(g_wl2 + (kt * 16 + nt) * 64 + boff2));
                mma_bf16(c1[nt], a0, a1, a2, a3, bb.x, bb.y);
            }
        }

        // t = ssp(C1 + b2) packed -> stage-B A-frags
        uint32_t p_lo[16], p_hi[16];
#pragma unroll
        for (int nt = 0; nt < 16; nt++) {
            float bA0 = sb2[nt * 8 + 2 * q], bA1 = sb2[nt * 8 + 2 * q + 1];
            p_lo[nt] = pack_bf2(sspf(c1[nt][0] + bA0), sspf(c1[nt][1] + bA1));
            p_hi[nt] = pack_bf2(sspf(c1[nt][2] + bA0), sspf(c1[nt][3] + bA1));
        }

        // ===== stage B: C2 = t @ lin3 (Lcol n) + b3 + x, store =====
#pragma unroll
        for (int nh = 0; nh < 2; nh++) {
            float c2[8][4];
#pragma unroll
            for (int nt = 0; nt < 8; nt++)
#pragma unroll
                for (int i = 0; i < 4; i++) c2[nt][i] = 0.f;

#pragma unroll
            for (int kt = 0; kt < 8; kt++) {
                uint32_t a0 = p_lo[2 * kt],     a1 = p_hi[2 * kt];
                uint32_t a2 = p_lo[2 * kt + 1], a3 = p_hi[2 * kt + 1];
#pragma unroll
                for (int nt = 0; nt < 8; nt++) {
                    uint2 bb = __ldg((const uint2*)(g_wl3 + (kt * 16 + nh * 8 + nt) * 64 + boff2));
                    mma_bf16(c2[nt], a0, a1, a2, a3, bb.x, bb.y);
                }
            }

#pragma unroll
            for (int th = 0; th < 4; th++) {
                int cn = nh * 64 + th * 16 + 4 * q;
                float4 b4 = *(const float4*)&sb3[cn];
                if (in0) {
                    float4 xv = *(const float4*)&x[r0 * 128 + cn];
                    float4 o;
                    o.x = xv.x + c2[2*th][0]   + b4.x;
                    o.y = xv.y + c2[2*th][1]   + b4.y;
                    o.z = xv.z + c2[2*th+1][0] + b4.z;
                    o.w = xv.w + c2[2*th+1][1] + b4.w;
                    *(float4*)&out[r0 * 128 + cn] = o;
                }
                if (in1) {
                    float4 xv = *(const float4*)&x[r1 * 128 + cn];
                    float4 o;
                    o.x = xv.x + c2[2*th][2]   + b4.x;
                    o.y = xv.y + c2[2*th][3]   + b4.y;
                    o.z = xv.z + c2[2*th+1][2] + b4.z;
                    o.w = xv.w + c2[2*th+1][3] + b4.w;
                    *(float4*)&out[r1 * 128 + cn] = o;
                }
            }
        }
    }
}

// ---------------------------------------------------------------------------

static const int SMEM1 = (128 * 128 + 128 + NW * 4 * 128) * 4;

extern "C" void kernel_launch(void* const* d_in, const int* in_sizes, int n_in,
                              void* d_out, int out_size)
{
    const float* x    = (const float*)d_in[0];
    const float* ea   = (const float*)d_in[1];
    const float* ew   = (const float*)d_in[2];
    const float* l1w  = (const float*)d_in[3];
    const float* l1b  = (const float*)d_in[4];
    const float* cf1  = (const float*)d_in[5];
    const float* cf2  = (const float*)d_in[6];
    const float* cf2b = (const float*)d_in[7];
    const float* l2w  = (const float*)d_in[8];
    const float* l2b  = (const float*)d_in[9];
    const float* l3w  = (const float*)d_in[10];
    const float* l3b  = (const float*)d_in[11];
    const int*   ei   = (const int*)d_in[12];

    int N = in_sizes[0] / 128;
    int E = in_sizes[1] / 64;
    int ntiles  = (E + 15) / 16;
    int ntilesN = (N + 15) / 16;

    cudaFuncSetAttribute(k_vproj, cudaFuncAttributeMaxDynamicSharedMemorySize, SMEM1);

    k_wprep   <<<56, 256>>>(cf1, cf2, l2w, l3w);
    k_vproj   <<<GRID, TPB, SMEM1>>>(x, l1w, l1b, N);
    k_edge_mma<<<296, 256>>>(ea, ew, cf2b, ei, E, N, ntiles);
    k_post_mma<<<296, 256>>>(x, l2b, l3b, (float*)d_out, N, ntilesN);
}

// round 17
// speedup vs baseline: 4.8709x; 1.2507x over previous
#include <cuda_runtime.h>
#include <cstdint>

// ---------------------------------------------------------------------------
// SchNet interaction block — all four GEMM layers on bf16 mma.sync.
//   K0: pre-permute cf1/cf2/lin1/lin2/lin3 into bf16-pair global scratch
//   K1: v = x@lin1+b1 (bf16 mma, Lcol epilogue) ; zero g_agg
//   K2: edge filter net (bf16 mma) + gather(prefetched)/modulate/red.v4
//   K3: out = x + ssp(agg@lin2+b2)@lin3 + b3 (bf16 mma)
// Base-target sm_103: mma.sync only. edge_index = int32 (verified R3).
// ---------------------------------------------------------------------------

#define N_NODES 100000
#define H 128

#define W1B   (4 * 16 * 64)     // ea->h1   (k=64)
#define W2B   (8 * 16 * 64)     // h1->h2   (k=128, Lcol)
#define WL1   (8 * 16 * 64)     // x->v     (k=128, Lcol)
#define WL2   (8 * 16 * 64)     // agg->t   (k=128)
#define WL3   (8 * 16 * 64)     // t->out   (k=128, Lcol)

__device__ __align__(128) float g_v[N_NODES * H];
__device__ __align__(128) float g_agg[N_NODES * H];
__device__ __align__(128) uint32_t g_w1b[W1B];
__device__ __align__(128) uint32_t g_w2b[W2B];
__device__ __align__(128) uint32_t g_wl1[WL1];
__device__ __align__(128) uint32_t g_wl2[WL2];
__device__ __align__(128) uint32_t g_wl3[WL3];

#define LN2F 0.69314718055994530942f
#define L2EF 1.44269504088896340736f

__device__ __forceinline__ float ex2f(float x) {
    float r; asm("ex2.approx.f32 %0, %1;" : "=f"(r) : "f"(x)); return r;
}
__device__ __forceinline__ float lg2f(float x) {
    float r; asm("lg2.approx.f32 %0, %1;" : "=f"(r) : "f"(x)); return r;
}
__device__ __forceinline__ float sspf(float z) {
    float t = ex2f(-fabsf(z) * L2EF);
    float u = lg2f(1.0f + t);
    return fmaxf(z, 0.0f) + fmaf(u, LN2F, -LN2F);
}

__device__ __forceinline__ uint32_t pack_bf2(float lo, float hi) {
    uint32_t r; asm("cvt.rn.bf16x2.f32 %0, %1, %2;" : "=r"(r) : "f"(hi), "f"(lo));
    return r;
}
__device__ __forceinline__ void mma_bf16(float c[4], uint32_t a0, uint32_t a1,
                                         uint32_t a2, uint32_t a3,
                                         uint32_t b0, uint32_t b1) {
    asm volatile("mma.sync.aligned.m16n8k16.row.col.f32.bf16.bf16.f32 "
                 "{%0,%1,%2,%3}, {%4,%5,%6,%7}, {%8,%9}, {%0,%1,%2,%3};"
                 : "+f"(c[0]), "+f"(c[1]), "+f"(c[2]), "+f"(c[3])
                 : "r"(a0), "r"(a1), "r"(a2), "r"(a3), "r"(b0), "r"(b1));
}
__device__ __forceinline__ void red4(float* p, float m0, float m1, float m2, float m3) {
    asm volatile("red.global.add.v4.f32 [%0], {%1, %2, %3, %4};"
                 :: "l"(p), "f"(m0), "f"(m1), "f"(m2), "f"(m3) : "memory");
}

// Lcol: output-column permutation pairing adjacent n8 blocks so thread q owns
// 4 consecutive logical cols.
__device__ __forceinline__ int Lcol(int nt, int n) {
    return 16 * (nt >> 1) + 4 * (n >> 1) + 2 * (nt & 1) + (n & 1);
}

// ---------------------------------------------------------------------------
// K0: weight prep (bf16 pairs, 64-u32 block per (kt16, nt8)).
// ---------------------------------------------------------------------------
__global__ void k_wprep(const float* __restrict__ cf1, const float* __restrict__ cf2,
                        const float* __restrict__ l1w, const float* __restrict__ l2w,
                        const float* __restrict__ l3w)
{
    int stride = blockDim.x * gridDim.x;
    int t0 = blockIdx.x * blockDim.x + threadIdx.x;
    for (int f = t0; f < W1B; f += stride) {
        int block = f >> 6, j = f & 63;
        int kt = block >> 4, nt = block & 15;
        int lane = j >> 1, reg = j & 1;
        int k = kt * 16 + 2 * (lane & 3) + reg * 8;
        int n = nt * 8 + (lane >> 2);
        g_w1b[f] = pack_bf2(cf1[k * 128 + n], cf1[(k + 1) * 128 + n]);
    }
    for (int f = t0; f < W2B; f += stride) {
        int block = f >> 6, j = f & 63;
        int kt = block >> 4, nt = block & 15;
        int lane = j >> 1, reg = j & 1;
        int k = kt * 16 + 2 * (lane & 3) + reg * 8;
        int n = Lcol(nt, lane >> 2);
        g_w2b[f] = pack_bf2(cf2[k * 128 + n], cf2[(k + 1) * 128 + n]);
    }
    for (int f = t0; f < WL1; f += stride) {
        int block = f >> 6, j = f & 63;
        int kt = block >> 4, nt = block & 15;
        int lane = j >> 1, reg = j & 1;
        int k = kt * 16 + 2 * (lane & 3) + reg * 8;
        int n = Lcol(nt, lane >> 2);
        g_wl1[f] = pack_bf2(l1w[k * 128 + n], l1w[(k + 1) * 128 + n]);
    }
    for (int f = t0; f < WL2; f += stride) {
        int block = f >> 6, j = f & 63;
        int kt = block >> 4, nt = block & 15;
        int lane = j >> 1, reg = j & 1;
        int k = kt * 16 + 2 * (lane & 3) + reg * 8;
        int n = nt * 8 + (lane >> 2);
        g_wl2[f] = pack_bf2(l2w[k * 128 + n], l2w[(k + 1) * 128 + n]);
    }
    for (int f = t0; f < WL3; f += stride) {
        int block = f >> 6, j = f & 63;
        int kt = block >> 4, nt = block & 15;
        int lane = j >> 1, reg = j & 1;
        int k = kt * 16 + 2 * (lane & 3) + reg * 8;
        int n = Lcol(nt, lane >> 2);
        g_wl3[f] = pack_bf2(l3w[k * 128 + n], l3w[(k + 1) * 128 + n]);
    }
}

// ---------------------------------------------------------------------------
// K1: v = x@lin1 + b1 via bf16 mma (Lcol epilogue); zero g_agg.
// ---------------------------------------------------------------------------
__global__ void __launch_bounds__(256, 2)
k_vproj_mma(const float* __restrict__ x, const float* __restrict__ b1,
            int N, int ntiles)
{
    __shared__ float sb1[128];
    const int tid = threadIdx.x;
    if (tid < 128) sb1[tid] = b1[tid];
    __syncthreads();

    const int wid = tid >> 5;
    const int lane = tid & 31;
    const int rg = lane >> 2;
    const int q = lane & 3;
    const int boff2 = lane * 2;

    const long wstride = (long)gridDim.x * 8;

    for (long tile = (long)blockIdx.x * 8 + wid; tile < ntiles; tile += wstride) {
        const long tb = tile * 16;
        const long r0 = tb + rg;
        const long r1 = r0 + 8;
        const bool in0 = r0 < N, in1 = r1 < N;

        float c[16][4];
#pragma unroll
        for (int nt = 0; nt < 16; nt++)
#pragma unroll
            for (int i = 0; i < 4; i++) c[nt][i] = 0.f;

#pragma unroll
        for (int kt = 0; kt < 8; kt++) {
            int cb = kt * 16 + 2 * q;
            float2 f0 = in0 ? *(const float2*)&x[r0 * 128 + cb]     : make_float2(0.f, 0.f);
            float2 f1 = in1 ? *(const float2*)&x[r1 * 128 + cb]     : make_float2(0.f, 0.f);
            float2 f2 = in0 ? *(const float2*)&x[r0 * 128 + cb + 8] : make_float2(0.f, 0.f);
            float2 f3 = in1 ? *(const float2*)&x[r1 * 128 + cb + 8] : make_float2(0.f, 0.f);
            uint32_t a0 = pack_bf2(f0.x, f0.y);
            uint32_t a1 = pack_bf2(f1.x, f1.y);
            uint32_t a2 = pack_bf2(f2.x, f2.y);
            uint32_t a3 = pack_bf2(f3.x, f3.y);
#pragma unroll
            for (int nt = 0; nt < 16; nt++) {
                uint2 bb = __ldg((const uint2*)(g_wl1 + (kt * 16 + nt) * 64 + boff2));
                mma_bf16(c[nt], a0, a1, a2, a3, bb.x, bb.y);
            }
        }

#pragma unroll
        for (int th = 0; th < 8; th++) {
            int cn = th * 16 + 4 * q;
            float4 b4 = *(const float4*)&sb1[cn];
            if (in0) {
                float4 o = make_float4(c[2*th][0] + b4.x, c[2*th][1] + b4.y,
                                       c[2*th+1][0] + b4.z, c[2*th+1][1] + b4.w);
                *(float4*)&g_v[r0 * 128 + cn] = o;
                *(float4*)&g_agg[r0 * 128 + cn] = make_float4(0.f, 0.f, 0.f, 0.f);
            }
            if (in1) {
                float4 o = make_float4(c[2*th][2] + b4.x, c[2*th][3] + b4.y,
                                       c[2*th+1][2] + b4.z, c[2*th+1][3] + b4.w);
                *(float4*)&g_v[r1 * 128 + cn] = o;
                *(float4*)&g_agg[r1 * 128 + cn] = make_float4(0.f, 0.f, 0.f, 0.f);
            }
        }
    }
}

// ---------------------------------------------------------------------------
// K2: bf16 mma edge kernel; v[src] gather prefetched ahead of stage-2 mma.
// ---------------------------------------------------------------------------
__global__ void __launch_bounds__(256, 2)
k_edge_mma(const float* __restrict__ ea, const float* __restrict__ ew,
           const float* __restrict__ cf2b, const int* __restrict__ ei,
           int E, int N, int ntiles)
{
    __shared__ float sbias[128];
    const int tid = threadIdx.x;
    if (tid < 128) sbias[tid] = cf2b[tid];
    __syncthreads();

    const int wid = tid >> 5;
    const int lane = tid & 31;
    const int rg = lane >> 2;
    const int q = lane & 3;
    const int boff2 = lane * 2;

    const long wstride = (long)gridDim.x * 8;

    for (long tile = (long)blockIdx.x * 8 + wid; tile < ntiles; tile += wstride) {
        const long tb = tile * 16;
        const long r0 = tb + rg;
        const long r1 = r0 + 8;
        const bool in0 = r0 < E, in1 = r1 < E;

        // edge metadata first: s0/s1 ready before gather prefetch below
        bool v0 = in0, v1 = in1;
        int s0 = 0, d0 = 0, s1 = 0, d1 = 0;
        float w0 = 0.f, w1 = 0.f;
        if (v0) {
            s0 = ei[r0]; d0 = ei[E + r0]; w0 = ew[r0];
            if ((unsigned)s0 >= (unsigned)N || (unsigned)d0 >= (unsigned)N) v0 = false;
        }
        if (v1) {
            s1 = ei[r1]; d1 = ei[E + r1]; w1 = ew[r1];
            if ((unsigned)s1 >= (unsigned)N || (unsigned)d1 >= (unsigned)N) v1 = false;
        }

        // ========== stage 1: C1 = EA[16,64] @ W1 ==========
        float c1[16][4];
#pragma unroll
        for (int nt = 0; nt < 16; nt++)
#pragma unroll
            for (int i = 0; i < 4; i++) c1[nt][i] = 0.f;

#pragma unroll
        for (int kt = 0; kt < 4; kt++) {
            int cb = kt * 16 + 2 * q;
            float2 f0 = in0 ? __ldg((const float2*)(ea + r0 * 64 + cb))     : make_float2(0.f, 0.f);
            float2 f1 = in1 ? __ldg((const float2*)(ea + r1 * 64 + cb))     : make_float2(0.f, 0.f);
            float2 f2 = in0 ? __ldg((const float2*)(ea + r0 * 64 + cb + 8)) : make_float2(0.f, 0.f);
            float2 f3 = in1 ? __ldg((const float2*)(ea + r1 * 64 + cb + 8)) : make_float2(0.f, 0.f);
            uint32_t a0 = pack_bf2(f0.x, f0.y);
            uint32_t a1 = pack_bf2(f1.x, f1.y);
            uint32_t a2 = pack_bf2(f2.x, f2.y);
            uint32_t a3 = pack_bf2(f3.x, f3.y);
#pragma unroll
            for (int nt = 0; nt < 16; nt++) {
                uint2 bb = __ldg((const uint2*)(g_w1b + (kt * 16 + nt) * 64 + boff2));
                mma_bf16(c1[nt], a0, a1, a2, a3, bb.x, bb.y);
            }
        }

        // h1 = ssp(C1) packed — stage-2 A-frags.
        uint32_t p_lo[16], p_hi[16];
#pragma unroll
        for (int nt = 0; nt < 16; nt++) {
            p_lo[nt] = pack_bf2(sspf(c1[nt][0]), sspf(c1[nt][1]));
            p_hi[nt] = pack_bf2(sspf(c1[nt][2]), sspf(c1[nt][3]));
        }

        // ========== stage 2 (n-halves), gather prefetched ahead of mma =====
#pragma unroll
        for (int nh = 0; nh < 2; nh++) {
            // prefetch v[src] for this half: latency hides under 64 mma below
            float4 pv0[4], pv1[4];
#pragma unroll
            for (int th = 0; th < 4; th++) {
                int cn = nh * 64 + th * 16 + 4 * q;
                pv0[th] = v0 ? *(const float4*)&g_v[(long)s0 * 128 + cn]
                             : make_float4(0.f, 0.f, 0.f, 0.f);
                pv1[th] = v1 ? *(const float4*)&g_v[(long)s1 * 128 + cn]
                             : make_float4(0.f, 0.f, 0.f, 0.f);
            }

            float c2[8][4];
#pragma unroll
            for (int nt = 0; nt < 8; nt++)
#pragma unroll
                for (int i = 0; i < 4; i++) c2[nt][i] = 0.f;

#pragma unroll
            for (int kt = 0; kt < 8; kt++) {
                uint32_t a0 = p_lo[2 * kt],     a1 = p_hi[2 * kt];
                uint32_t a2 = p_lo[2 * kt + 1], a3 = p_hi[2 * kt + 1];
#pragma unroll
                for (int nt = 0; nt < 8; nt++) {
                    uint2 bb = __ldg((const uint2*)(g_w2b + (kt * 16 + nh * 8 + nt) * 64 + boff2));
                    mma_bf16(c2[nt], a0, a1, a2, a3, bb.x, bb.y);
                }
            }

            // ---- float4 epilogue ----
#pragma unroll
            for (int th = 0; th < 4; th++) {
                int cn = nh * 64 + th * 16 + 4 * q;
                float4 b4 = *(const float4*)&sbias[cn];
                if (v0) {
                    float h0 = sspf(c2[2*th][0]   + b4.x);
                    float h1 = sspf(c2[2*th][1]   + b4.y);
                    float h2 = sspf(c2[2*th+1][0] + b4.z);
                    float h3 = sspf(c2[2*th+1][1] + b4.w);
                    red4(&g_agg[(long)d0 * 128 + cn],
                         pv0[th].x * h0 * w0, pv0[th].y * h1 * w0,
                         pv0[th].z * h2 * w0, pv0[th].w * h3 * w0);
                }
                if (v1) {
                    float h0 = sspf(c2[2*th][2]   + b4.x);
                    float h1 = sspf(c2[2*th][3]   + b4.y);
                    float h2 = sspf(c2[2*th+1][2] + b4.z);
                    float h3 = sspf(c2[2*th+1][3] + b4.w);
                    red4(&g_agg[(long)d1 * 128 + cn],
                         pv1[th].x * h0 * w1, pv1[th].y * h1 * w1,
                         pv1[th].z * h2 * w1, pv1[th].w * h3 * w1);
                }
            }
        }
    }
}

// ---------------------------------------------------------------------------
// K3: post MLP + residual via bf16 mma (unchanged from R15).
// ---------------------------------------------------------------------------
__global__ void __launch_bounds__(256, 2)
k_post_mma(const float* __restrict__ x, const float* __restrict__ b2,
           const float* __restrict__ b3, float* __restrict__ out,
           int N, int ntiles)
{
    __shared__ float sb2[128], sb3[128];
    const int tid = threadIdx.x;
    if (tid < 128) { sb2[tid] = b2[tid]; sb3[tid] = b3[tid]; }
    __syncthreads();

    const int wid = tid >> 5;
    const int lane = tid & 31;
    const int rg = lane >> 2;
    const int q = lane & 3;
    const int boff2 = lane * 2;

    const long wstride = (long)gridDim.x * 8;

    for (long tile = (long)blockIdx.x * 8 + wid; tile < ntiles; tile += wstride) {
        const long tb = tile * 16;
        const long r0 = tb + rg;
        const long r1 = r0 + 8;
        const bool in0 = r0 < N, in1 = r1 < N;

        float c1[16][4];
#pragma unroll
        for (int nt = 0; nt < 16; nt++)
#pragma unroll
            for (int i = 0; i < 4; i++) c1[nt][i] = 0.f;

#pragma unroll
        for (int kt = 0; kt < 8; kt++) {
            int cb = kt * 16 + 2 * q;
            float2 f0 = in0 ? *(const float2*)&g_agg[r0 * 128 + cb]     : make_float2(0.f, 0.f);
            float2 f1 = in1 ? *(const float2*)&g_agg[r1 * 128 + cb]     : make_float2(0.f, 0.f);
            float2 f2 = in0 ? *(const float2*)&g_agg[r0 * 128 + cb + 8] : make_float2(0.f, 0.f);
            float2 f3 = in1 ? *(const float2*)&g_agg[r1 * 128 + cb + 8] : make_float2(0.f, 0.f);
            uint32_t a0 = pack_bf2(f0.x, f0.y);
            uint32_t a1 = pack_bf2(f1.x, f1.y);
            uint32_t a2 = pack_bf2(f2.x, f2.y);
            uint32_t a3 = pack_bf2(f3.x, f3.y);
#pragma unroll
            for (int nt = 0; nt < 16; nt++) {
                uint2 bb = __ldg((const uint2*)(g_wl2 + (kt * 16 + nt) * 64 + boff2));
                mma_bf16(c1[nt], a0, a1, a2, a3, bb.x, bb.y);
            }
        }

        uint32_t p_lo[16], p_hi[16];
#pragma unroll
        for (int nt = 0; nt < 16; nt++) {
            float bA0 = sb2[nt * 8 + 2 * q], bA1 = sb2[nt * 8 + 2 * q + 1];
            p_lo[nt] = pack_bf2(sspf(c1[nt][0] + bA0), sspf(c1[nt][1] + bA1));
            p_hi[nt] = pack_bf2(sspf(c1[nt][2] + bA0), sspf(c1[nt][3] + bA1));
        }

#pragma unroll
        for (int nh = 0; nh < 2; nh++) {
            float c2[8][4];
#pragma unroll
            for (int nt = 0; nt < 8; nt++)
#pragma unroll
                for (int i = 0; i < 4; i++) c2[nt][i] = 0.f;

#pragma unroll
            for (int kt = 0; kt < 8; kt++) {
                uint32_t a0 = p_lo[2 * kt],     a1 = p_hi[2 * kt];
                uint32_t a2 = p_lo[2 * kt + 1], a3 = p_hi[2 * kt + 1];
#pragma unroll
                for (int nt = 0; nt < 8; nt++) {
                    uint2 bb = __ldg((const uint2*)(g_wl3 + (kt * 16 + nh * 8 + nt) * 64 + boff2));
                    mma_bf16(c2[nt], a0, a1, a2, a3, bb.x, bb.y);
                }
            }

#pragma unroll
            for (int th = 0; th < 4; th++) {
                int cn = nh * 64 + th * 16 + 4 * q;
                float4 b4 = *(const float4*)&sb3[cn];
                if (in0) {
                    float4 xv = *(const float4*)&x[r0 * 128 + cn];
                    float4 o;
                    o.x = xv.x + c2[2*th][0]   + b4.x;
                    o.y = xv.y + c2[2*th][1]   + b4.y;
                    o.z = xv.z + c2[2*th+1][0] + b4.z;
                    o.w = xv.w + c2[2*th+1][1] + b4.w;
                    *(float4*)&out[r0 * 128 + cn] = o;
                }
                if (in1) {
                    float4 xv = *(const float4*)&x[r1 * 128 + cn];
                    float4 o;
                    o.x = xv.x + c2[2*th][2]   + b4.x;
                    o.y = xv.y + c2[2*th][3]   + b4.y;
                    o.z = xv.z + c2[2*th+1][2] + b4.z;
                    o.w = xv.w + c2[2*th+1][3] + b4.w;
                    *(float4*)&out[r1 * 128 + cn] = o;
                }
            }
        }
    }
}

// ---------------------------------------------------------------------------

extern "C" void kernel_launch(void* const* d_in, const int* in_sizes, int n_in,
                              void* d_out, int out_size)
{
    const float* x    = (const float*)d_in[0];
    const float* ea   = (const float*)d_in[1];
    const float* ew   = (const float*)d_in[2];
    const float* l1w  = (const float*)d_in[3];
    const float* l1b  = (const float*)d_in[4];
    const float* cf1  = (const float*)d_in[5];
    const float* cf2  = (const float*)d_in[6];
    const float* cf2b = (const float*)d_in[7];
    const float* l2w  = (const float*)d_in[8];
    const float* l2b  = (const float*)d_in[9];
    const float* l3w  = (const float*)d_in[10];
    const float* l3b  = (const float*)d_in[11];
    const int*   ei   = (const int*)d_in[12];

    int N = in_sizes[0] / 128;
    int E = in_sizes[1] / 64;
    int ntiles  = (E + 15) / 16;
    int ntilesN = (N + 15) / 16;

    k_wprep    <<<72, 256>>>(cf1, cf2, l1w, l2w, l3w);
    k_vproj_mma<<<296, 256>>>(x, l1b, N, ntilesN);
    k_edge_mma <<<296, 256>>>(ea, ew, cf2b, ei, E, N, ntiles);
    k_post_mma <<<296, 256>>>(x, l2b, l3b, (float*)d_out, N, ntilesN);
}